// round 4
// baseline (speedup 1.0000x reference)
#include <cuda_runtime.h>
#include <cstdint>

#define EPSF 1.1920928955078125e-07f

// Problem constants
#define B_   32
#define P_   8192
#define SI_  64
#define SO_  32
#define L_   256
#define C_   4096          // 2 * SI * SO
#define YSZ  33554432      // B*P*128
#define PST  130           // padded p-stride (even -> 8B-aligned pair loads)

// Device scratch (no allocations allowed)
__device__ float g_logits[B_ * C_];
__device__ float g_V[B_ * C_];
__device__ float g_mask[B_ * C_];
__device__ float g_hp[16 * B_ * L_];   // split-K partials for h

// ---------------------------------------------------------------------------
// Kernel 1: logits[b,c] = sum_l latent[b,l] * K[side(c)][l, i, o]
// ---------------------------------------------------------------------------
__global__ void __launch_bounds__(256) k_logits(const float* __restrict__ lat,
                                                const float* __restrict__ Kl,
                                                const float* __restrict__ Kr) {
    __shared__ float slat[B_ * L_];  // 32 KB
    for (int k = threadIdx.x; k < B_ * L_; k += 256) slat[k] = lat[k];
    __syncthreads();

    int c  = blockIdx.x * 32 + (threadIdx.x & 31);
    int bg = threadIdx.x >> 5;                // 0..7 -> batches bg*4..bg*4+3
    const float* Ksrc = (c & 2048) ? Kr : Kl;
    int cc = c & 2047;

    float acc[4] = {0.f, 0.f, 0.f, 0.f};
#pragma unroll 4
    for (int l = 0; l < L_; l++) {
        float kv = Ksrc[(size_t)l * 2048 + cc];
#pragma unroll
        for (int q = 0; q < 4; q++)
            acc[q] += slat[(bg * 4 + q) * L_ + l] * kv;
    }
#pragma unroll
    for (int q = 0; q < 4; q++)
        g_logits[(bg * 4 + q) * C_ + c] = acc[q];
}

// ---------------------------------------------------------------------------
// Kernel 2: warp-per-(b,side,o) column softmax + gumbel-softmax.
// ---------------------------------------------------------------------------
__device__ __forceinline__ float warp_max(float v) {
#pragma unroll
    for (int m = 16; m > 0; m >>= 1) v = fmaxf(v, __shfl_xor_sync(0xffffffffu, v, m));
    return v;
}
__device__ __forceinline__ float warp_sum(float v) {
#pragma unroll
    for (int m = 16; m > 0; m >>= 1) v += __shfl_xor_sync(0xffffffffu, v, m);
    return v;
}

__global__ void __launch_bounds__(256) k_sg(const float* __restrict__ gu,
                                            const float* __restrict__ temp) {
    int w    = (blockIdx.x * blockDim.x + threadIdx.x) >> 5;  // 0..2047
    int lane = threadIdx.x & 31;
    int rem  = w & 63;
    int base = (w >> 6) * C_ + (rem >> 5) * 2048 + (rem & 31);

    float a0 = g_logits[base + lane * 32];
    float a1 = g_logits[base + (lane + 32) * 32];
    float mx = warp_max(fmaxf(a0, a1));
    float e0 = __expf(a0 - mx), e1 = __expf(a1 - mx);
    float inv = 1.0f / warp_sum(e0 + e1);
    float p0 = e0 * inv, p1 = e1 * inv;
    g_V[base + lane * 32]        = p0;
    g_V[base + (lane + 32) * 32] = p1;

    float tc = fmaxf(fminf(fmaxf(temp[0], EPSF), 2.0f), EPSF);
    float invt = 1.0f / tc;

    float u0 = fmaxf(gu[base + lane * 32], EPSF);
    float u1 = fmaxf(gu[base + (lane + 32) * 32], EPSF);
    float g0 = -__logf(-__logf(u0) + EPSF);
    float g1 = -__logf(-__logf(u1) + EPSF);
    float l0 = (__logf(p0 + EPSF) + g0) * invt;
    float l1 = (__logf(p1 + EPSF) + g1) * invt;
    mx = warp_max(fmaxf(l0, l1));
    e0 = __expf(l0 - mx); e1 = __expf(l1 - mx);
    inv = 1.0f / warp_sum(e0 + e1);
    g_mask[base + lane * 32]        = e0 * inv;
    g_mask[base + (lane + 32) * 32] = e1 * inv;
}

// ---------------------------------------------------------------------------
// Kernel 3: split-K h partials; W1 read exactly once (4 MB).
// ---------------------------------------------------------------------------
__global__ void __launch_bounds__(128) k_h_part(const float* __restrict__ W1) {
    int jt = blockIdx.x & 7;
    int ks = blockIdx.x >> 3;

    __shared__ float Vs[B_ * 260];
    for (int idx = threadIdx.x; idx < B_ * 256; idx += 128) {
        int b = idx >> 8, k = idx & 255;
        Vs[b * 260 + k] = g_V[b * C_ + ks * 256 + k];
    }
    __syncthreads();

    int j  = jt * 32 + (threadIdx.x & 31);
    int bq = threadIdx.x >> 5;

    float acc[8];
#pragma unroll
    for (int q = 0; q < 8; q++) acc[q] = 0.f;

#pragma unroll 4
    for (int k = 0; k < 256; k++) {
        float wv = W1[(size_t)(ks * 256 + k) * 256 + j];
#pragma unroll
        for (int q = 0; q < 8; q++)
            acc[q] += Vs[(bq * 8 + q) * 260 + k] * wv;
    }
#pragma unroll
    for (int q = 0; q < 8; q++)
        g_hp[(ks * B_ + bq * 8 + q) * L_ + j] = acc[q];
}

// ---------------------------------------------------------------------------
// Kernel 4 (main GEMM): block 256 thr, tile 128p x 64o, thread 4p x 4o x 2side.
// Packed-over-p fma.rn.f32x2; masks pre-duplicated in smem as (m,m) pairs,
// x transposed in smem -> zero per-step packing movs. Dynamic smem 49.4 KB.
// grid (64 p-tiles, 32 batches).
// ---------------------------------------------------------------------------
#define FMA2(acc, a, m) asm("fma.rn.f32x2 %0, %1, %2, %0;" : "+l"(acc) : "l"(a), "l"(m))
#define UNPK(lo, hi, s) asm("mov.b64 {%0, %1}, %2;" : "=f"(lo), "=f"(hi) : "l"(s))

extern __shared__ float dynsm[];

__global__ void __launch_bounds__(256) k_main(const float* __restrict__ x,
                                              float* __restrict__ y) {
    float2* smd = (float2*)dynsm;            // 4096 float2 duplicated masks
    float*  xs  = dynsm + 8192;              // 32 x PST transposed x chunk

    int tid = threadIdx.x;
    int b = blockIdx.y;
    int pbase = blockIdx.x * 128;

    // masks duplicated: g_mask (side,i,o) -> smd[i*64 + side*32 + o] = (m, m)
    for (int idx = tid; idx < C_; idx += 256) {
        int side = idx >> 11, rem = idx & 2047;
        float v = g_mask[b * C_ + idx];
        smd[(rem >> 5) * 64 + side * 32 + (rem & 31)] = make_float2(v, v);
    }

    int og = tid & 7, pg = tid >> 3;         // og 0..7, pg 0..31
    int o0 = og * 4, p0 = pg * 4;

    unsigned long long aL[4][2], aR[4][2];   // [o][p-pair]
#pragma unroll
    for (int o = 0; o < 4; o++) { aL[o][0] = aL[o][1] = 0ULL; aR[o][0] = aR[o][1] = 0ULL; }

    const float* xg = x + ((size_t)b * P_ + pbase) * SI_;

#pragma unroll
    for (int ic = 0; ic < 2; ic++) {
        __syncthreads();
        // stage 128p x 32i transposed (4 float4 per thread)
#pragma unroll
        for (int k = 0; k < 4; k++) {
            int idx = tid + k * 256;          // 0..1023
            int p = idx >> 3, f = idx & 7;
            float4 v = *(const float4*)(xg + (size_t)p * SI_ + ic * 32 + f * 4);
            xs[(f * 4 + 0) * PST + p] = v.x;
            xs[(f * 4 + 1) * PST + p] = v.y;
            xs[(f * 4 + 2) * PST + p] = v.z;
            xs[(f * 4 + 3) * PST + p] = v.w;
        }
        __syncthreads();

#pragma unroll 8
        for (int ii = 0; ii < 32; ii++) {
            int i = ic * 32 + ii;
            const unsigned long long* xp = (const unsigned long long*)(xs + ii * PST + p0);
            unsigned long long x0 = xp[0], x1 = xp[1];       // p-pairs (p0,p0+1),(p0+2,p0+3)
            ulonglong2 mA = *(const ulonglong2*)(smd + i * 64 + o0);       // yl o0+0, o0+1
            ulonglong2 mB = *(const ulonglong2*)(smd + i * 64 + o0 + 2);   // yl o0+2, o0+3
            ulonglong2 mC = *(const ulonglong2*)(smd + i * 64 + 32 + o0);  // yr o0+0, o0+1
            ulonglong2 mD = *(const ulonglong2*)(smd + i * 64 + 32 + o0 + 2);
            FMA2(aL[0][0], x0, mA.x); FMA2(aL[0][1], x1, mA.x);
            FMA2(aL[1][0], x0, mA.y); FMA2(aL[1][1], x1, mA.y);
            FMA2(aL[2][0], x0, mB.x); FMA2(aL[2][1], x1, mB.x);
            FMA2(aL[3][0], x0, mB.y); FMA2(aL[3][1], x1, mB.y);
            FMA2(aR[0][0], x0, mC.x); FMA2(aR[0][1], x1, mC.x);
            FMA2(aR[1][0], x0, mC.y); FMA2(aR[1][1], x1, mC.y);
            FMA2(aR[2][0], x0, mD.x); FMA2(aR[2][1], x1, mD.x);
            FMA2(aR[3][0], x0, mD.y); FMA2(aR[3][1], x1, mD.y);
        }
    }

    // epilogue: thread owns rows p0..p0+3, cols o0..o0+3
    float* yb = y + ((size_t)b * P_ + pbase) * 128;
#define CLIP01(v) fminf(fmaxf((v), 0.f), 1.f)
#pragma unroll
    for (int pp = 0; pp < 2; pp++) {
        float l[2][4], r[2][4];
#pragma unroll
        for (int o = 0; o < 4; o++) {
            UNPK(l[0][o], l[1][o], aL[o][pp]);
            UNPK(r[0][o], r[1][o], aR[o][pp]);
        }
#pragma unroll
        for (int rr = 0; rr < 2; rr++) {
            float* row = yb + (size_t)(p0 + pp * 2 + rr) * 128 + o0;
            float s0 = l[rr][0] + r[rr][0], s1 = l[rr][1] + r[rr][1];
            float s2 = l[rr][2] + r[rr][2], s3 = l[rr][3] + r[rr][3];
            float d0 = l[rr][0] - r[rr][0], d1 = l[rr][1] - r[rr][1];
            float d2 = l[rr][2] - r[rr][2], d3 = l[rr][3] - r[rr][3];
            float4 v;
            v.x = CLIP01(s0); v.y = CLIP01(s1); v.z = CLIP01(s2); v.w = CLIP01(s3);
            *(float4*)(row) = v;
            v.x = CLIP01(s0 - 1.f); v.y = CLIP01(s1 - 1.f); v.z = CLIP01(s2 - 1.f); v.w = CLIP01(s3 - 1.f);
            *(float4*)(row + 32) = v;
            v.x = CLIP01(d0); v.y = CLIP01(d1); v.z = CLIP01(d2); v.w = CLIP01(d3);
            *(float4*)(row + 64) = v;
            v.x = CLIP01(-d0); v.y = CLIP01(-d1); v.z = CLIP01(-d2); v.w = CLIP01(-d3);
            *(float4*)(row + 96) = v;
        }
    }
#undef CLIP01
}

// ---------------------------------------------------------------------------
// Kernel 5: reduce h partials + leaky, then v_encode = h @ W2 + b2.
// grid 32 x 1024 (256 j x 4 K-slices, smem reduce).
// ---------------------------------------------------------------------------
__global__ void __launch_bounds__(1024) k_venc(const float* __restrict__ b1,
                                               const float* __restrict__ W2,
                                               const float* __restrict__ b2,
                                               float* __restrict__ out) {
    int b = blockIdx.x;
    int tid = threadIdx.x;
    __shared__ float sh[L_];
    __shared__ float red[4][L_];

    if (tid < L_) {
        float s = b1[tid];
#pragma unroll
        for (int ks = 0; ks < 16; ks++) s += g_hp[(ks * B_ + b) * L_ + tid];
        sh[tid] = (s >= 0.f) ? s : 0.01f * s;
    }
    __syncthreads();

    int j = tid & 255, sl = tid >> 8;
    float a = 0.f;
    const float* wp = W2 + (size_t)(sl * 64) * L_ + j;
#pragma unroll 8
    for (int k = 0; k < 64; k++)
        a += sh[sl * 64 + k] * wp[(size_t)k * L_];
    red[sl][j] = a;
    __syncthreads();
    if (sl == 0)
        out[YSZ + b * L_ + j] = red[0][j] + red[1][j] + red[2][j] + red[3][j] + b2[j];
}

// ---------------------------------------------------------------------------
extern "C" void kernel_launch(void* const* d_in, const int* in_sizes, int n_in,
                              void* d_out, int out_size) {
    const float* x    = (const float*)d_in[0];
    const float* lat  = (const float*)d_in[1];
    const float* gu   = (const float*)d_in[2];
    const float* Kl   = (const float*)d_in[3];
    const float* Kr   = (const float*)d_in[4];
    const float* temp = (const float*)d_in[5];
    const float* W1   = (const float*)d_in[6];
    const float* b1   = (const float*)d_in[7];
    const float* W2   = (const float*)d_in[8];
    const float* b2   = (const float*)d_in[9];
    float* out = (float*)d_out;

    const int SMEM = (8192 + 32 * PST) * 4;   // 49,408 B dynamic smem
    static_assert((8192 + 32 * PST) * 4 < 100 * 1024, "smem");
    cudaFuncSetAttribute(k_main, cudaFuncAttributeMaxDynamicSharedMemorySize, SMEM);

    k_logits<<<128, 256>>>(lat, Kl, Kr);
    k_sg<<<256, 256>>>(gu, temp);
    k_h_part<<<128, 128>>>(W1);
    k_main<<<dim3(64, 32), 256, SMEM>>>(x, out);   // slot 4: ncu-sampled
    k_venc<<<32, 1024>>>(b1, W2, b2, out);
}

// round 5
// speedup vs baseline: 1.4819x; 1.4819x over previous
#include <cuda_runtime.h>
#include <cstdint>

#define EPSF 1.1920928955078125e-07f

// Problem constants
#define B_   32
#define P_   8192
#define SI_  64
#define SO_  32
#define L_   256
#define C_   4096          // 2 * SI * SO
#define YSZ  33554432      // B*P*128
#define PST2 260           // padded p-stride, 16B-aligned rows (260*4 = 65*16)

// Device scratch (no allocations allowed)
__device__ float g_logits[B_ * C_];
__device__ float g_V[B_ * C_];
__device__ float g_mask[B_ * C_];
__device__ float g_hp[32 * B_ * L_];   // 32-way split-K partials for h

// ---------------------------------------------------------------------------
// Kernel 1: logits[b,c] = sum_l latent[b,l] * K[side(c)][l, i, o]
// grid (128 c-tiles, 2 b-halves) x 256 thr; unroll-8 K loads for MLP.
// ---------------------------------------------------------------------------
__global__ void __launch_bounds__(256) k_logits(const float* __restrict__ lat,
                                                const float* __restrict__ Kl,
                                                const float* __restrict__ Kr) {
    __shared__ float slat[16 * L_];  // 16 batches x 256
    int bt = blockIdx.y;
    for (int k = threadIdx.x; k < 16 * L_; k += 256)
        slat[k] = lat[bt * 16 * L_ + k];
    __syncthreads();

    int c  = blockIdx.x * 32 + (threadIdx.x & 31);
    int bg = threadIdx.x >> 5;                // 0..7 -> 2 batches each
    const float* Ksrc = (c & 2048) ? Kr : Kl;
    int cc = c & 2047;

    float a0 = 0.f, a1 = 0.f;
    const float* s0 = slat + (bg * 2) * L_;
    const float* s1 = s0 + L_;
#pragma unroll 2
    for (int l = 0; l < L_; l += 8) {
        float kv[8];
#pragma unroll
        for (int u = 0; u < 8; u++) kv[u] = Ksrc[(size_t)(l + u) * 2048 + cc];
#pragma unroll
        for (int u = 0; u < 8; u++) {
            a0 += s0[l + u] * kv[u];
            a1 += s1[l + u] * kv[u];
        }
    }
    int b = bt * 16 + bg * 2;
    g_logits[(size_t)b * C_ + c]       = a0;
    g_logits[(size_t)(b + 1) * C_ + c] = a1;
}

// ---------------------------------------------------------------------------
// Kernel 2: block per (b, side): coalesced smem staging, warp-per-i-slice,
// cross-warp reductions in smem. Softmax over i (V), then gumbel-softmax.
// grid 64 x 256 (8 warps; warp w owns i = 8w..8w+7; lane = o).
// ---------------------------------------------------------------------------
__global__ void __launch_bounds__(256) k_sg(const float* __restrict__ gu,
                                            const float* __restrict__ temp) {
    __shared__ float sl[SI_ * 33];   // staged [i][o] padded
    __shared__ float red[8][32];
    __shared__ float red2[8][32];

    int b = blockIdx.x >> 1, side = blockIdx.x & 1;
    int tid = threadIdx.x, w = tid >> 5, lane = tid & 31;
    int gbase = b * C_ + side * 2048;

    for (int idx = tid; idx < 2048; idx += 256)
        sl[(idx >> 5) * 33 + (idx & 31)] = g_logits[gbase + idx];
    __syncthreads();

    float v[8];
    float mx = -1e30f;
#pragma unroll
    for (int k = 0; k < 8; k++) { v[k] = sl[(w * 8 + k) * 33 + lane]; mx = fmaxf(mx, v[k]); }
    red[w][lane] = mx;
    __syncthreads();
    float gm = red[0][lane];
#pragma unroll
    for (int q = 1; q < 8; q++) gm = fmaxf(gm, red[q][lane]);
    float s = 0.f;
#pragma unroll
    for (int k = 0; k < 8; k++) { v[k] = __expf(v[k] - gm); s += v[k]; }
    red2[w][lane] = s;
    __syncthreads();
    float tot = 0.f;
#pragma unroll
    for (int q = 0; q < 8; q++) tot += red2[q][lane];
    float inv = 1.0f / tot;
#pragma unroll
    for (int k = 0; k < 8; k++) { v[k] *= inv; g_V[gbase + (w * 8 + k) * 32 + lane] = v[k]; }

    __syncthreads();   // sl reads done; safe to restage
    for (int idx = tid; idx < 2048; idx += 256)
        sl[(idx >> 5) * 33 + (idx & 31)] = gu[gbase + idx];
    __syncthreads();

    float tc = fmaxf(fminf(fmaxf(temp[0], EPSF), 2.0f), EPSF);
    float invt = 1.0f / tc;

    mx = -1e30f;
#pragma unroll
    for (int k = 0; k < 8; k++) {
        float u = fmaxf(sl[(w * 8 + k) * 33 + lane], EPSF);
        float g = -__logf(-__logf(u) + EPSF);
        float lg = (__logf(v[k] + EPSF) + g) * invt;
        v[k] = lg; mx = fmaxf(mx, lg);
    }
    red[w][lane] = mx;
    __syncthreads();
    gm = red[0][lane];
#pragma unroll
    for (int q = 1; q < 8; q++) gm = fmaxf(gm, red[q][lane]);
    s = 0.f;
#pragma unroll
    for (int k = 0; k < 8; k++) { v[k] = __expf(v[k] - gm); s += v[k]; }
    red2[w][lane] = s;
    __syncthreads();
    tot = 0.f;
#pragma unroll
    for (int q = 0; q < 8; q++) tot += red2[q][lane];
    inv = 1.0f / tot;
#pragma unroll
    for (int k = 0; k < 8; k++)
        g_mask[gbase + (w * 8 + k) * 32 + lane] = v[k] * inv;
}

// ---------------------------------------------------------------------------
// Kernel 3: 32-way split-K h partials. grid 256 = (8 jt x 32 ks),
// block 256 = (32 j x 8 b-groups of 4). W1 read exactly once.
// ---------------------------------------------------------------------------
__global__ void __launch_bounds__(256) k_h_part(const float* __restrict__ W1) {
    int jt = blockIdx.x & 7;
    int ks = blockIdx.x >> 3;   // 0..31, 128 k each

    __shared__ float Vs[B_ * 132];
    for (int idx = threadIdx.x; idx < B_ * 128; idx += 256) {
        int b = idx >> 7, k = idx & 127;
        Vs[b * 132 + k] = g_V[b * C_ + ks * 128 + k];
    }
    __syncthreads();

    int j  = jt * 32 + (threadIdx.x & 31);
    int bg = threadIdx.x >> 5;

    float acc[4] = {0.f, 0.f, 0.f, 0.f};
#pragma unroll 4
    for (int k = 0; k < 128; k++) {
        float wv = W1[(size_t)(ks * 128 + k) * 256 + j];
#pragma unroll
        for (int q = 0; q < 4; q++)
            acc[q] += Vs[(bg * 4 + q) * 132 + k] * wv;
    }
#pragma unroll
    for (int q = 0; q < 4; q++)
        g_hp[(size_t)(ks * B_ + bg * 4 + q) * L_ + j] = acc[q];
}

// ---------------------------------------------------------------------------
// Kernel 4 (main GEMM): block 256 thr, tile 256p x 64c, thread 8p x 4o x 2side.
// 32 u64 accumulators, packed-over-p fma.rn.f32x2; masks dup'd (m,m) in smem,
// x transposed in smem. Per i-step: 6 LDS.128 for 32 FMA2 -> FMA-pipe bound.
// grid (32 p-tiles, 32 batches); dynamic smem 66 KB, 2 blocks/SM.
// ---------------------------------------------------------------------------
#define FMA2(acc, a, m) asm("fma.rn.f32x2 %0, %1, %2, %0;" : "+l"(acc) : "l"(a), "l"(m))
#define UNPK(lo, hi, s) asm("mov.b64 {%0, %1}, %2;" : "=f"(lo), "=f"(hi) : "l"(s))

extern __shared__ float dynsm[];

__global__ void __launch_bounds__(256, 2) k_main(const float* __restrict__ x,
                                                 float* __restrict__ y) {
    float2* smd = (float2*)dynsm;            // 4096 float2 dup masks (32 KB)
    float*  xs  = dynsm + 8192;              // 32 x PST2 transposed x (33.3 KB)

    int tid = threadIdx.x;
    int b = blockIdx.y;
    int pbase = blockIdx.x * 256;

    // masks duplicated: g_mask (side,i,o) -> smd[i*64 + side*32 + o] = (m, m)
    for (int idx = tid; idx < C_; idx += 256) {
        int side = idx >> 11, rem = idx & 2047;
        float v = g_mask[b * C_ + idx];
        smd[(rem >> 5) * 64 + side * 32 + (rem & 31)] = make_float2(v, v);
    }

    int og = tid & 7, pg = tid >> 3;         // og 0..7, pg 0..31
    int o0 = og * 4, p0 = pg * 8;

    unsigned long long aL[4][4], aR[4][4];   // [o][p-pair]
#pragma unroll
    for (int o = 0; o < 4; o++)
#pragma unroll
        for (int j = 0; j < 4; j++) { aL[o][j] = 0ULL; aR[o][j] = 0ULL; }

    const float* xg = x + ((size_t)b * P_ + pbase) * SI_;

#pragma unroll
    for (int ic = 0; ic < 2; ic++) {
        __syncthreads();
        // stage 256p x 32i transposed (8 float4 per thread)
#pragma unroll
        for (int k = 0; k < 8; k++) {
            int idx = tid + k * 256;          // 0..2047
            int p = idx >> 3, f = idx & 7;
            float4 v = *(const float4*)(xg + (size_t)p * SI_ + ic * 32 + f * 4);
            xs[(f * 4 + 0) * PST2 + p] = v.x;
            xs[(f * 4 + 1) * PST2 + p] = v.y;
            xs[(f * 4 + 2) * PST2 + p] = v.z;
            xs[(f * 4 + 3) * PST2 + p] = v.w;
        }
        __syncthreads();

#pragma unroll 4
        for (int ii = 0; ii < 32; ii++) {
            int i = ic * 32 + ii;
            ulonglong2 xA = *(const ulonglong2*)(xs + ii * PST2 + p0);      // pairs 0,1
            ulonglong2 xB = *(const ulonglong2*)(xs + ii * PST2 + p0 + 4);  // pairs 2,3
            ulonglong2 mA = *(const ulonglong2*)(smd + i * 64 + o0);        // yl o0, o0+1
            ulonglong2 mB = *(const ulonglong2*)(smd + i * 64 + o0 + 2);    // yl o0+2, o0+3
            ulonglong2 mC = *(const ulonglong2*)(smd + i * 64 + 32 + o0);   // yr o0, o0+1
            ulonglong2 mD = *(const ulonglong2*)(smd + i * 64 + 32 + o0 + 2);
            FMA2(aL[0][0], xA.x, mA.x); FMA2(aL[0][1], xA.y, mA.x);
            FMA2(aL[0][2], xB.x, mA.x); FMA2(aL[0][3], xB.y, mA.x);
            FMA2(aL[1][0], xA.x, mA.y); FMA2(aL[1][1], xA.y, mA.y);
            FMA2(aL[1][2], xB.x, mA.y); FMA2(aL[1][3], xB.y, mA.y);
            FMA2(aL[2][0], xA.x, mB.x); FMA2(aL[2][1], xA.y, mB.x);
            FMA2(aL[2][2], xB.x, mB.x); FMA2(aL[2][3], xB.y, mB.x);
            FMA2(aL[3][0], xA.x, mB.y); FMA2(aL[3][1], xA.y, mB.y);
            FMA2(aL[3][2], xB.x, mB.y); FMA2(aL[3][3], xB.y, mB.y);
            FMA2(aR[0][0], xA.x, mC.x); FMA2(aR[0][1], xA.y, mC.x);
            FMA2(aR[0][2], xB.x, mC.x); FMA2(aR[0][3], xB.y, mC.x);
            FMA2(aR[1][0], xA.x, mC.y); FMA2(aR[1][1], xA.y, mC.y);
            FMA2(aR[1][2], xB.x, mC.y); FMA2(aR[1][3], xB.y, mC.y);
            FMA2(aR[2][0], xA.x, mD.x); FMA2(aR[2][1], xA.y, mD.x);
            FMA2(aR[2][2], xB.x, mD.x); FMA2(aR[2][3], xB.y, mD.x);
            FMA2(aR[3][0], xA.x, mD.y); FMA2(aR[3][1], xA.y, mD.y);
            FMA2(aR[3][2], xB.x, mD.y); FMA2(aR[3][3], xB.y, mD.y);
        }
    }

    // epilogue: thread owns rows p0..p0+7, cols o0..o0+3 (both sides)
    float* yb = y + ((size_t)b * P_ + pbase) * 128;
#define CLIP01(v) fminf(fmaxf((v), 0.f), 1.f)
#pragma unroll
    for (int pp = 0; pp < 4; pp++) {
        float l[2][4], r[2][4];
#pragma unroll
        for (int o = 0; o < 4; o++) {
            UNPK(l[0][o], l[1][o], aL[o][pp]);
            UNPK(r[0][o], r[1][o], aR[o][pp]);
        }
#pragma unroll
        for (int rr = 0; rr < 2; rr++) {
            float* row = yb + (size_t)(p0 + pp * 2 + rr) * 128 + o0;
            float s0 = l[rr][0] + r[rr][0], s1 = l[rr][1] + r[rr][1];
            float s2 = l[rr][2] + r[rr][2], s3 = l[rr][3] + r[rr][3];
            float d0 = l[rr][0] - r[rr][0], d1 = l[rr][1] - r[rr][1];
            float d2 = l[rr][2] - r[rr][2], d3 = l[rr][3] - r[rr][3];
            float4 v;
            v.x = CLIP01(s0); v.y = CLIP01(s1); v.z = CLIP01(s2); v.w = CLIP01(s3);
            *(float4*)(row) = v;
            v.x = CLIP01(s0 - 1.f); v.y = CLIP01(s1 - 1.f); v.z = CLIP01(s2 - 1.f); v.w = CLIP01(s3 - 1.f);
            *(float4*)(row + 32) = v;
            v.x = CLIP01(d0); v.y = CLIP01(d1); v.z = CLIP01(d2); v.w = CLIP01(d3);
            *(float4*)(row + 64) = v;
            v.x = CLIP01(-d0); v.y = CLIP01(-d1); v.z = CLIP01(-d2); v.w = CLIP01(-d3);
            *(float4*)(row + 96) = v;
        }
    }
#undef CLIP01
}

// ---------------------------------------------------------------------------
// Kernel 5: reduce 32 h partials + leaky, then v_encode = h @ W2 + b2.
// grid 32 x 1024 (256 j x 4 K-slices, smem reduce).
// ---------------------------------------------------------------------------
__global__ void __launch_bounds__(1024) k_venc(const float* __restrict__ b1,
                                               const float* __restrict__ W2,
                                               const float* __restrict__ b2,
                                               float* __restrict__ out) {
    int b = blockIdx.x;
    int tid = threadIdx.x;
    __shared__ float sh[L_];
    __shared__ float red[4][L_];

    if (tid < L_) {
        float s = b1[tid];
#pragma unroll 8
        for (int ks = 0; ks < 32; ks++) s += g_hp[(size_t)(ks * B_ + b) * L_ + tid];
        sh[tid] = (s >= 0.f) ? s : 0.01f * s;
    }
    __syncthreads();

    int j = tid & 255, sl = tid >> 8;
    float a = 0.f;
    const float* wp = W2 + (size_t)(sl * 64) * L_ + j;
#pragma unroll 8
    for (int k = 0; k < 64; k++)
        a += sh[sl * 64 + k] * wp[(size_t)k * L_];
    red[sl][j] = a;
    __syncthreads();
    if (sl == 0)
        out[YSZ + b * L_ + j] = red[0][j] + red[1][j] + red[2][j] + red[3][j] + b2[j];
}

// ---------------------------------------------------------------------------
extern "C" void kernel_launch(void* const* d_in, const int* in_sizes, int n_in,
                              void* d_out, int out_size) {
    const float* x    = (const float*)d_in[0];
    const float* lat  = (const float*)d_in[1];
    const float* gu   = (const float*)d_in[2];
    const float* Kl   = (const float*)d_in[3];
    const float* Kr   = (const float*)d_in[4];
    const float* temp = (const float*)d_in[5];
    const float* W1   = (const float*)d_in[6];
    const float* b1   = (const float*)d_in[7];
    const float* W2   = (const float*)d_in[8];
    const float* b2   = (const float*)d_in[9];
    float* out = (float*)d_out;

    const int SMEM = (8192 + 32 * PST2) * 4;   // 66,048 B dynamic smem
    static_assert((8192 + 32 * PST2) * 4 < 120 * 1024, "smem");
    cudaFuncSetAttribute(k_main, cudaFuncAttributeMaxDynamicSharedMemorySize, SMEM);

    k_logits<<<dim3(128, 2), 256>>>(lat, Kl, Kr);
    k_sg<<<64, 256>>>(gu, temp);
    k_h_part<<<256, 256>>>(W1);
    k_main<<<dim3(32, 32), 256, SMEM>>>(x, out);   // slot 4: ncu-sampled
    k_venc<<<32, 1024>>>(b1, W2, b2, out);
}

// round 6
// speedup vs baseline: 2.0936x; 1.4128x over previous
#include <cuda_runtime.h>
#include <cuda_bf16.h>
#include <cstdint>

#define EPSF 1.1920928955078125e-07f

// Problem constants
#define B_   32
#define P_   8192
#define SI_  64
#define SO_  32
#define L_   256
#define C_   4096          // 2 * SI * SO
#define YSZ  33554432      // B*P*128

// Device scratch (no allocations allowed)
__device__ float g_logits[B_ * C_];
__device__ float g_V[B_ * C_];
__device__ float g_hp[32 * B_ * L_];          // 32-way split-K partials for h
__device__ __nv_bfloat16 g_mh[B_ * C_];       // mask hi (bf16)
__device__ __nv_bfloat16 g_ml[B_ * C_];       // mask lo residual (bf16)

// ---------------------------------------------------------------------------
// Kernel 1: logits[b,c] = sum_l latent[b,l] * K[side(c)][l, i, o]
// ---------------------------------------------------------------------------
__global__ void __launch_bounds__(256) k_logits(const float* __restrict__ lat,
                                                const float* __restrict__ Kl,
                                                const float* __restrict__ Kr) {
    __shared__ float slat[16 * L_];
    int bt = blockIdx.y;
    for (int k = threadIdx.x; k < 16 * L_; k += 256)
        slat[k] = lat[bt * 16 * L_ + k];
    __syncthreads();

    int c  = blockIdx.x * 32 + (threadIdx.x & 31);
    int bg = threadIdx.x >> 5;
    const float* Ksrc = (c & 2048) ? Kr : Kl;
    int cc = c & 2047;

    float a0 = 0.f, a1 = 0.f;
    const float* s0 = slat + (bg * 2) * L_;
    const float* s1 = s0 + L_;
#pragma unroll 2
    for (int l = 0; l < L_; l += 8) {
        float kv[8];
#pragma unroll
        for (int u = 0; u < 8; u++) kv[u] = Ksrc[(size_t)(l + u) * 2048 + cc];
#pragma unroll
        for (int u = 0; u < 8; u++) {
            a0 += s0[l + u] * kv[u];
            a1 += s1[l + u] * kv[u];
        }
    }
    int b = bt * 16 + bg * 2;
    g_logits[(size_t)b * C_ + c]       = a0;
    g_logits[(size_t)(b + 1) * C_ + c] = a1;
}

// ---------------------------------------------------------------------------
// Kernel 2: block per (b, side): softmax over i (-> g_V), gumbel-softmax
// (-> g_mh/g_ml bf16 hi/lo split). grid 64 x 256.
// ---------------------------------------------------------------------------
__global__ void __launch_bounds__(256) k_sg(const float* __restrict__ gu,
                                            const float* __restrict__ temp) {
    __shared__ float sl[SI_ * 33];
    __shared__ float red[8][32];
    __shared__ float red2[8][32];

    int b = blockIdx.x >> 1, side = blockIdx.x & 1;
    int tid = threadIdx.x, w = tid >> 5, lane = tid & 31;
    int gbase = b * C_ + side * 2048;

    for (int idx = tid; idx < 2048; idx += 256)
        sl[(idx >> 5) * 33 + (idx & 31)] = g_logits[gbase + idx];
    __syncthreads();

    float v[8];
    float mx = -1e30f;
#pragma unroll
    for (int k = 0; k < 8; k++) { v[k] = sl[(w * 8 + k) * 33 + lane]; mx = fmaxf(mx, v[k]); }
    red[w][lane] = mx;
    __syncthreads();
    float gm = red[0][lane];
#pragma unroll
    for (int q = 1; q < 8; q++) gm = fmaxf(gm, red[q][lane]);
    float s = 0.f;
#pragma unroll
    for (int k = 0; k < 8; k++) { v[k] = __expf(v[k] - gm); s += v[k]; }
    red2[w][lane] = s;
    __syncthreads();
    float tot = 0.f;
#pragma unroll
    for (int q = 0; q < 8; q++) tot += red2[q][lane];
    float inv = 1.0f / tot;
#pragma unroll
    for (int k = 0; k < 8; k++) { v[k] *= inv; g_V[gbase + (w * 8 + k) * 32 + lane] = v[k]; }

    __syncthreads();
    for (int idx = tid; idx < 2048; idx += 256)
        sl[(idx >> 5) * 33 + (idx & 31)] = gu[gbase + idx];
    __syncthreads();

    float tc = fmaxf(fminf(fmaxf(temp[0], EPSF), 2.0f), EPSF);
    float invt = 1.0f / tc;

    mx = -1e30f;
#pragma unroll
    for (int k = 0; k < 8; k++) {
        float u = fmaxf(sl[(w * 8 + k) * 33 + lane], EPSF);
        float g = -__logf(-__logf(u) + EPSF);
        float lg = (__logf(v[k] + EPSF) + g) * invt;
        v[k] = lg; mx = fmaxf(mx, lg);
    }
    red[w][lane] = mx;
    __syncthreads();
    gm = red[0][lane];
#pragma unroll
    for (int q = 1; q < 8; q++) gm = fmaxf(gm, red[q][lane]);
    s = 0.f;
#pragma unroll
    for (int k = 0; k < 8; k++) { v[k] = __expf(v[k] - gm); s += v[k]; }
    red2[w][lane] = s;
    __syncthreads();
    tot = 0.f;
#pragma unroll
    for (int q = 0; q < 8; q++) tot += red2[q][lane];
    inv = 1.0f / tot;

    // masks -> bf16 hi/lo split, layout [b][i][side*32 + o]
#pragma unroll
    for (int k = 0; k < 8; k++) {
        float mv = v[k] * inv;
        __nv_bfloat16 hi = __float2bfloat16_rn(mv);
        __nv_bfloat16 lo = __float2bfloat16_rn(mv - __bfloat162float(hi));
        size_t idx = (size_t)b * C_ + (w * 8 + k) * 64 + side * 32 + lane;
        g_mh[idx] = hi;
        g_ml[idx] = lo;
    }
}

// ---------------------------------------------------------------------------
// Kernel 3: 32-way split-K h partials. W1 read exactly once.
// ---------------------------------------------------------------------------
__global__ void __launch_bounds__(256) k_h_part(const float* __restrict__ W1) {
    int jt = blockIdx.x & 7;
    int ks = blockIdx.x >> 3;

    __shared__ float Vs[B_ * 132];
    for (int idx = threadIdx.x; idx < B_ * 128; idx += 256) {
        int b = idx >> 7, k = idx & 127;
        Vs[b * 132 + k] = g_V[b * C_ + ks * 128 + k];
    }
    __syncthreads();

    int j  = jt * 32 + (threadIdx.x & 31);
    int bg = threadIdx.x >> 5;

    float acc[4] = {0.f, 0.f, 0.f, 0.f};
#pragma unroll 4
    for (int k = 0; k < 128; k++) {
        float wv = W1[(size_t)(ks * 128 + k) * 256 + j];
#pragma unroll
        for (int q = 0; q < 4; q++)
            acc[q] += Vs[(bg * 4 + q) * 132 + k] * wv;
    }
#pragma unroll
    for (int q = 0; q < 4; q++)
        g_hp[(size_t)(ks * B_ + bg * 4 + q) * L_ + j] = acc[q];
}

// ---------------------------------------------------------------------------
// Kernel 4 (main GEMM, tensor cores): per batch Y[8192,64] = X[8192,64(i)] @
// M[64(i),64(c)]. bf16 3-term split: Xh*Mh + Xl*Mh + Xh*Ml, fp32 accum.
// Block = 256 thr (8 warps), tile = 128 rows; warp = 16 rows (m16n8k16).
// smem rows padded to 144B -> conflict-free LDSM. grid (64 p-tiles, 32 b).
// ---------------------------------------------------------------------------
#define LDSM4(r, a) \
    asm volatile("ldmatrix.sync.aligned.m8n8.x4.shared.b16 {%0,%1,%2,%3}, [%4];" \
        : "=r"((r)[0]), "=r"((r)[1]), "=r"((r)[2]), "=r"((r)[3]) : "r"(a))
#define LDSM4T(r, a) \
    asm volatile("ldmatrix.sync.aligned.m8n8.x4.trans.shared.b16 {%0,%1,%2,%3}, [%4];" \
        : "=r"((r)[0]), "=r"((r)[1]), "=r"((r)[2]), "=r"((r)[3]) : "r"(a))
#define MMA16816(d, a, b0, b1) \
    asm volatile("mma.sync.aligned.m16n8k16.row.col.f32.bf16.bf16.f32 " \
        "{%0,%1,%2,%3}, {%4,%5,%6,%7}, {%8,%9}, {%0,%1,%2,%3};" \
        : "+f"((d)[0]), "+f"((d)[1]), "+f"((d)[2]), "+f"((d)[3]) \
        : "r"((a)[0]), "r"((a)[1]), "r"((a)[2]), "r"((a)[3]), "r"(b0), "r"(b1))

// smem byte offsets (rows padded: 64 bf16 -> 144 B, 16B-multiple)
#define SM_MH 0
#define SM_ML 9216
#define SM_XH 18432
#define SM_XL 36864
#define SM_TOT 55296

extern __shared__ char smc[];

__global__ void __launch_bounds__(256) k_main(const float* __restrict__ x,
                                              float* __restrict__ y) {
    int tid = threadIdx.x, lane = tid & 31, w = tid >> 5;
    int b = blockIdx.y;
    int pbase = blockIdx.x * 128;

    uint32_t sb = (uint32_t)__cvta_generic_to_shared(smc);

    // stage masks (bf16 hi/lo), 64 rows x 128B -> padded 144B rows
    const uint4* mh4 = (const uint4*)(g_mh + (size_t)b * C_);
    const uint4* ml4 = (const uint4*)(g_ml + (size_t)b * C_);
#pragma unroll
    for (int k = 0; k < 2; k++) {
        int idx = tid + k * 256;          // 0..511 = 64 rows x 8 chunks
        int row = idx >> 3, ch = idx & 7;
        *(uint4*)(smc + SM_MH + row * 144 + ch * 16) = mh4[idx];
        *(uint4*)(smc + SM_ML + row * 144 + ch * 16) = ml4[idx];
    }

    // stage X: load f32, split to bf16 hi + lo residual
    const float4* xg = (const float4*)(x + ((size_t)b * P_ + pbase) * SI_);
#pragma unroll
    for (int k = 0; k < 8; k++) {
        int idx = tid + k * 256;          // 0..2047 = 128 rows x 16 float4
        int row = idx >> 4, f4 = idx & 15;
        float4 v = xg[idx];
        __nv_bfloat16 h0 = __float2bfloat16_rn(v.x);
        __nv_bfloat16 h1 = __float2bfloat16_rn(v.y);
        __nv_bfloat16 h2 = __float2bfloat16_rn(v.z);
        __nv_bfloat16 h3 = __float2bfloat16_rn(v.w);
        __nv_bfloat16 l0 = __float2bfloat16_rn(v.x - __bfloat162float(h0));
        __nv_bfloat16 l1 = __float2bfloat16_rn(v.y - __bfloat162float(h1));
        __nv_bfloat16 l2 = __float2bfloat16_rn(v.z - __bfloat162float(h2));
        __nv_bfloat16 l3 = __float2bfloat16_rn(v.w - __bfloat162float(h3));
        __nv_bfloat162 hA = {h0, h1}, hB = {h2, h3};
        __nv_bfloat162 lA = {l0, l1}, lB = {l2, l3};
        uint2 hp = make_uint2(*(uint32_t*)&hA, *(uint32_t*)&hB);
        uint2 lp = make_uint2(*(uint32_t*)&lA, *(uint32_t*)&lB);
        *(uint2*)(smc + SM_XH + row * 144 + f4 * 8) = hp;
        *(uint2*)(smc + SM_XL + row * 144 + f4 * 8) = lp;
    }
    __syncthreads();

    float d[8][4];
#pragma unroll
    for (int nt = 0; nt < 8; nt++)
#pragma unroll
        for (int q = 0; q < 4; q++) d[nt][q] = 0.f;

    // ldmatrix lane addressing: row = lane&15, +16B column offset for lanes>=16
    int lrow = lane & 15;
    uint32_t lcol = (lane >> 4) * 16;

#pragma unroll
    for (int ks = 0; ks < 4; ks++) {
        uint32_t ah[4], al[4];
        uint32_t aoff = (uint32_t)((w * 16 + lrow) * 144 + ks * 32) + lcol;
        LDSM4(ah, sb + SM_XH + aoff);
        LDSM4(al, sb + SM_XL + aoff);

        uint32_t bh[4][4], bl[4][4];
        uint32_t brow = (uint32_t)((ks * 16 + lrow) * 144) + lcol;
#pragma unroll
        for (int np = 0; np < 4; np++) {
            LDSM4T(bh[np], sb + SM_MH + brow + np * 32);
            LDSM4T(bl[np], sb + SM_ML + brow + np * 32);
        }
#pragma unroll
        for (int nt = 0; nt < 8; nt++) {
            uint32_t bh0 = bh[nt >> 1][(nt & 1) * 2], bh1 = bh[nt >> 1][(nt & 1) * 2 + 1];
            uint32_t bl0 = bl[nt >> 1][(nt & 1) * 2], bl1 = bl[nt >> 1][(nt & 1) * 2 + 1];
            MMA16816(d[nt], ah, bh0, bh1);
            MMA16816(d[nt], al, bh0, bh1);
            MMA16816(d[nt], ah, bl0, bl1);
        }
    }

    // epilogue: n-tiles 0-3 = yl cols, 4-7 = yr same cols (thread-local pairing)
    float* yb = y + ((size_t)b * P_ + pbase) * 128;
    int r0 = w * 16 + (lane >> 2);
    int jc = (lane & 3) * 2;
#define CLIP01(v) fminf(fmaxf((v), 0.f), 1.f)
#pragma unroll
    for (int nt = 0; nt < 4; nt++) {
        int col = nt * 8 + jc;
#pragma unroll
        for (int half = 0; half < 2; half++) {
            int p = r0 + half * 8;
            float l0 = d[nt][half * 2],     l1 = d[nt][half * 2 + 1];
            float q0 = d[nt + 4][half * 2], q1 = d[nt + 4][half * 2 + 1];
            float s0 = l0 + q0, s1 = l1 + q1;
            float e0 = l0 - q0, e1 = l1 - q1;
            float* row = yb + (size_t)p * 128 + col;
            *(float2*)(row)      = make_float2(CLIP01(s0),       CLIP01(s1));
            *(float2*)(row + 32) = make_float2(CLIP01(s0 - 1.f), CLIP01(s1 - 1.f));
            *(float2*)(row + 64) = make_float2(CLIP01(e0),       CLIP01(e1));
            *(float2*)(row + 96) = make_float2(CLIP01(-e0),      CLIP01(-e1));
        }
    }
#undef CLIP01
}

// ---------------------------------------------------------------------------
// Kernel 5: reduce 32 h partials + leaky, then v_encode = h @ W2 + b2.
// ---------------------------------------------------------------------------
__global__ void __launch_bounds__(1024) k_venc(const float* __restrict__ b1,
                                               const float* __restrict__ W2,
                                               const float* __restrict__ b2,
                                               float* __restrict__ out) {
    int b = blockIdx.x;
    int tid = threadIdx.x;
    __shared__ float sh[L_];
    __shared__ float red[4][L_];

    if (tid < L_) {
        float s = b1[tid];
#pragma unroll 8
        for (int ks = 0; ks < 32; ks++) s += g_hp[(size_t)(ks * B_ + b) * L_ + tid];
        sh[tid] = (s >= 0.f) ? s : 0.01f * s;
    }
    __syncthreads();

    int j = tid & 255, sl = tid >> 8;
    float a = 0.f;
    const float* wp = W2 + (size_t)(sl * 64) * L_ + j;
#pragma unroll 8
    for (int k = 0; k < 64; k++)
        a += sh[sl * 64 + k] * wp[(size_t)k * L_];
    red[sl][j] = a;
    __syncthreads();
    if (sl == 0)
        out[YSZ + b * L_ + j] = red[0][j] + red[1][j] + red[2][j] + red[3][j] + b2[j];
}

// ---------------------------------------------------------------------------
extern "C" void kernel_launch(void* const* d_in, const int* in_sizes, int n_in,
                              void* d_out, int out_size) {
    const float* x    = (const float*)d_in[0];
    const float* lat  = (const float*)d_in[1];
    const float* gu   = (const float*)d_in[2];
    const float* Kl   = (const float*)d_in[3];
    const float* Kr   = (const float*)d_in[4];
    const float* temp = (const float*)d_in[5];
    const float* W1   = (const float*)d_in[6];
    const float* b1   = (const float*)d_in[7];
    const float* W2   = (const float*)d_in[8];
    const float* b2   = (const float*)d_in[9];
    float* out = (float*)d_out;

    cudaFuncSetAttribute(k_main, cudaFuncAttributeMaxDynamicSharedMemorySize, SM_TOT);

    k_logits<<<dim3(128, 2), 256>>>(lat, Kl, Kr);
    k_sg<<<64, 256>>>(gu, temp);
    k_main<<<dim3(64, 32), 256, SM_TOT>>>(x, out);   // slot 3
    k_h_part<<<256, 256>>>(W1);                      // overlaps k_main
    k_venc<<<32, 1024>>>(b1, W2, b2, out);
}

// round 7
// speedup vs baseline: 2.3180x; 1.1072x over previous
#include <cuda_runtime.h>
#include <cuda_bf16.h>
#include <cstdint>

#define EPSF 1.1920928955078125e-07f

// Problem constants
#define B_   32
#define P_   8192
#define SI_  64
#define SO_  32
#define L_   256
#define C_   4096          // 2 * SI * SO
#define YSZ  33554432      // B*P*128

// Device scratch (no allocations allowed)
__device__ float g_logits[B_ * C_];
__device__ float g_V[B_ * C_];
__device__ float g_hp[64 * B_ * L_];          // 64-way split-K partials for h
__device__ __nv_bfloat16 g_mh[B_ * C_];       // mask hi (bf16)
__device__ __nv_bfloat16 g_ml[B_ * C_];       // mask lo residual (bf16)

// ---------------------------------------------------------------------------
// Kernel 1: logits[b,c] = sum_l latent[b,l] * K[side(c)][l, i, o]
// ---------------------------------------------------------------------------
__global__ void __launch_bounds__(256) k_logits(const float* __restrict__ lat,
                                                const float* __restrict__ Kl,
                                                const float* __restrict__ Kr) {
    __shared__ float slat[16 * L_];
    int bt = blockIdx.y;
    for (int k = threadIdx.x; k < 16 * L_; k += 256)
        slat[k] = lat[bt * 16 * L_ + k];
    __syncthreads();

    int c  = blockIdx.x * 32 + (threadIdx.x & 31);
    int bg = threadIdx.x >> 5;
    const float* Ksrc = (c & 2048) ? Kr : Kl;
    int cc = c & 2047;

    float a0 = 0.f, a1 = 0.f;
    const float* s0 = slat + (bg * 2) * L_;
    const float* s1 = s0 + L_;
#pragma unroll 2
    for (int l = 0; l < L_; l += 8) {
        float kv[8];
#pragma unroll
        for (int u = 0; u < 8; u++) kv[u] = Ksrc[(size_t)(l + u) * 2048 + cc];
#pragma unroll
        for (int u = 0; u < 8; u++) {
            a0 += s0[l + u] * kv[u];
            a1 += s1[l + u] * kv[u];
        }
    }
    int b = bt * 16 + bg * 2;
    g_logits[(size_t)b * C_ + c]       = a0;
    g_logits[(size_t)(b + 1) * C_ + c] = a1;
}

// ---------------------------------------------------------------------------
// Kernel 2: block per (b, side): softmax over i (-> g_V), gumbel-softmax
// (-> g_mh/g_ml bf16 hi/lo split). grid 64 x 256.
// ---------------------------------------------------------------------------
__global__ void __launch_bounds__(256) k_sg(const float* __restrict__ gu,
                                            const float* __restrict__ temp) {
    __shared__ float sl[SI_ * 33];
    __shared__ float red[8][32];
    __shared__ float red2[8][32];

    int b = blockIdx.x >> 1, side = blockIdx.x & 1;
    int tid = threadIdx.x, w = tid >> 5, lane = tid & 31;
    int gbase = b * C_ + side * 2048;

    for (int idx = tid; idx < 2048; idx += 256)
        sl[(idx >> 5) * 33 + (idx & 31)] = g_logits[gbase + idx];
    __syncthreads();

    float v[8];
    float mx = -1e30f;
#pragma unroll
    for (int k = 0; k < 8; k++) { v[k] = sl[(w * 8 + k) * 33 + lane]; mx = fmaxf(mx, v[k]); }
    red[w][lane] = mx;
    __syncthreads();
    float gm = red[0][lane];
#pragma unroll
    for (int q = 1; q < 8; q++) gm = fmaxf(gm, red[q][lane]);
    float s = 0.f;
#pragma unroll
    for (int k = 0; k < 8; k++) { v[k] = __expf(v[k] - gm); s += v[k]; }
    red2[w][lane] = s;
    __syncthreads();
    float tot = 0.f;
#pragma unroll
    for (int q = 0; q < 8; q++) tot += red2[q][lane];
    float inv = 1.0f / tot;
#pragma unroll
    for (int k = 0; k < 8; k++) { v[k] *= inv; g_V[gbase + (w * 8 + k) * 32 + lane] = v[k]; }

    __syncthreads();
    for (int idx = tid; idx < 2048; idx += 256)
        sl[(idx >> 5) * 33 + (idx & 31)] = gu[gbase + idx];
    __syncthreads();

    float tc = fmaxf(fminf(fmaxf(temp[0], EPSF), 2.0f), EPSF);
    float invt = 1.0f / tc;

    mx = -1e30f;
#pragma unroll
    for (int k = 0; k < 8; k++) {
        float u = fmaxf(sl[(w * 8 + k) * 33 + lane], EPSF);
        float g = -__logf(-__logf(u) + EPSF);
        float lg = (__logf(v[k] + EPSF) + g) * invt;
        v[k] = lg; mx = fmaxf(mx, lg);
    }
    red[w][lane] = mx;
    __syncthreads();
    gm = red[0][lane];
#pragma unroll
    for (int q = 1; q < 8; q++) gm = fmaxf(gm, red[q][lane]);
    s = 0.f;
#pragma unroll
    for (int k = 0; k < 8; k++) { v[k] = __expf(v[k] - gm); s += v[k]; }
    red2[w][lane] = s;
    __syncthreads();
    tot = 0.f;
#pragma unroll
    for (int q = 0; q < 8; q++) tot += red2[q][lane];
    inv = 1.0f / tot;

    // masks -> bf16 hi/lo split, layout [b][i][side*32 + o]
#pragma unroll
    for (int k = 0; k < 8; k++) {
        float mv = v[k] * inv;
        __nv_bfloat16 hi = __float2bfloat16_rn(mv);
        __nv_bfloat16 lo = __float2bfloat16_rn(mv - __bfloat162float(hi));
        size_t idx = (size_t)b * C_ + (w * 8 + k) * 64 + side * 32 + lane;
        g_mh[idx] = hi;
        g_ml[idx] = lo;
    }
}

// ---------------------------------------------------------------------------
// Kernel 3: 64-way split-K h partials. grid 512 = (8 jt x 64 ks),
// block 256 = (32 j x 8 b-groups of 4). 64-k slices, unroll-8 prefetch.
// W1 (4 MB) read exactly once; latency hidden by MLP=8 + 3.5 blocks/SM.
// ---------------------------------------------------------------------------
__global__ void __launch_bounds__(256) k_h_part(const float* __restrict__ W1) {
    int jt = blockIdx.x & 7;
    int ks = blockIdx.x >> 3;   // 0..63, 64 k each

    __shared__ float Vs[B_ * 68];
    for (int idx = threadIdx.x; idx < B_ * 64; idx += 256) {
        int b = idx >> 6, k = idx & 63;
        Vs[b * 68 + k] = g_V[b * C_ + ks * 64 + k];
    }
    __syncthreads();

    int j  = jt * 32 + (threadIdx.x & 31);
    int bg = threadIdx.x >> 5;   // 0..7 -> batches bg*4..bg*4+3

    float acc[4] = {0.f, 0.f, 0.f, 0.f};
    const float* wp = W1 + (size_t)(ks * 64) * 256 + j;
#pragma unroll
    for (int kb = 0; kb < 8; kb++) {
        float wv[8];
#pragma unroll
        for (int u = 0; u < 8; u++) wv[u] = wp[(size_t)(kb * 8 + u) * 256];
#pragma unroll
        for (int u = 0; u < 8; u++) {
            int k = kb * 8 + u;
#pragma unroll
            for (int q = 0; q < 4; q++)
                acc[q] += Vs[(bg * 4 + q) * 68 + k] * wv[u];
        }
    }
#pragma unroll
    for (int q = 0; q < 4; q++)
        g_hp[(size_t)(ks * B_ + bg * 4 + q) * L_ + j] = acc[q];
}

// ---------------------------------------------------------------------------
// Kernel 4 (main GEMM, tensor cores): per batch Y[8192,64] = X[8192,64(i)] @
// M[64(i),64(c)]. bf16 3-term split: Xh*Mh + Xl*Mh + Xh*Ml, fp32 accum.
// Block = 256 thr (8 warps), tile = 128 rows; warp = 16 rows (m16n8k16).
// smem rows padded to 144B -> conflict-free LDSM. grid (64 p-tiles, 32 b).
// ---------------------------------------------------------------------------
#define LDSM4(r, a) \
    asm volatile("ldmatrix.sync.aligned.m8n8.x4.shared.b16 {%0,%1,%2,%3}, [%4];" \
        : "=r"((r)[0]), "=r"((r)[1]), "=r"((r)[2]), "=r"((r)[3]) : "r"(a))
#define LDSM4T(r, a) \
    asm volatile("ldmatrix.sync.aligned.m8n8.x4.trans.shared.b16 {%0,%1,%2,%3}, [%4];" \
        : "=r"((r)[0]), "=r"((r)[1]), "=r"((r)[2]), "=r"((r)[3]) : "r"(a))
#define MMA16816(d, a, b0, b1) \
    asm volatile("mma.sync.aligned.m16n8k16.row.col.f32.bf16.bf16.f32 " \
        "{%0,%1,%2,%3}, {%4,%5,%6,%7}, {%8,%9}, {%0,%1,%2,%3};" \
        : "+f"((d)[0]), "+f"((d)[1]), "+f"((d)[2]), "+f"((d)[3]) \
        : "r"((a)[0]), "r"((a)[1]), "r"((a)[2]), "r"((a)[3]), "r"(b0), "r"(b1))

// smem byte offsets (rows padded: 64 bf16 -> 144 B, 16B-multiple)
#define SM_MH 0
#define SM_ML 9216
#define SM_XH 18432
#define SM_XL 36864
#define SM_TOT 55296

extern __shared__ char smc[];

__global__ void __launch_bounds__(256) k_main(const float* __restrict__ x,
                                              float* __restrict__ y) {
    int tid = threadIdx.x, lane = tid & 31, w = tid >> 5;
    int b = blockIdx.y;
    int pbase = blockIdx.x * 128;

    uint32_t sb = (uint32_t)__cvta_generic_to_shared(smc);

    // stage masks (bf16 hi/lo), 64 rows x 128B -> padded 144B rows
    const uint4* mh4 = (const uint4*)(g_mh + (size_t)b * C_);
    const uint4* ml4 = (const uint4*)(g_ml + (size_t)b * C_);
#pragma unroll
    for (int k = 0; k < 2; k++) {
        int idx = tid + k * 256;          // 0..511 = 64 rows x 8 chunks
        int row = idx >> 3, ch = idx & 7;
        *(uint4*)(smc + SM_MH + row * 144 + ch * 16) = mh4[idx];
        *(uint4*)(smc + SM_ML + row * 144 + ch * 16) = ml4[idx];
    }

    // stage X: load f32, split to bf16 hi + lo residual
    const float4* xg = (const float4*)(x + ((size_t)b * P_ + pbase) * SI_);
#pragma unroll
    for (int k = 0; k < 8; k++) {
        int idx = tid + k * 256;          // 0..2047 = 128 rows x 16 float4
        int row = idx >> 4, f4 = idx & 15;
        float4 v = xg[idx];
        __nv_bfloat16 h0 = __float2bfloat16_rn(v.x);
        __nv_bfloat16 h1 = __float2bfloat16_rn(v.y);
        __nv_bfloat16 h2 = __float2bfloat16_rn(v.z);
        __nv_bfloat16 h3 = __float2bfloat16_rn(v.w);
        __nv_bfloat16 l0 = __float2bfloat16_rn(v.x - __bfloat162float(h0));
        __nv_bfloat16 l1 = __float2bfloat16_rn(v.y - __bfloat162float(h1));
        __nv_bfloat16 l2 = __float2bfloat16_rn(v.z - __bfloat162float(h2));
        __nv_bfloat16 l3 = __float2bfloat16_rn(v.w - __bfloat162float(h3));
        __nv_bfloat162 hA = {h0, h1}, hB = {h2, h3};
        __nv_bfloat162 lA = {l0, l1}, lB = {l2, l3};
        uint2 hp = make_uint2(*(uint32_t*)&hA, *(uint32_t*)&hB);
        uint2 lp = make_uint2(*(uint32_t*)&lA, *(uint32_t*)&lB);
        *(uint2*)(smc + SM_XH + row * 144 + f4 * 8) = hp;
        *(uint2*)(smc + SM_XL + row * 144 + f4 * 8) = lp;
    }
    __syncthreads();

    float d[8][4];
#pragma unroll
    for (int nt = 0; nt < 8; nt++)
#pragma unroll
        for (int q = 0; q < 4; q++) d[nt][q] = 0.f;

    // ldmatrix lane addressing: row = lane&15, +16B column offset for lanes>=16
    int lrow = lane & 15;
    uint32_t lcol = (lane >> 4) * 16;

#pragma unroll
    for (int ks = 0; ks < 4; ks++) {
        uint32_t ah[4], al[4];
        uint32_t aoff = (uint32_t)((w * 16 + lrow) * 144 + ks * 32) + lcol;
        LDSM4(ah, sb + SM_XH + aoff);
        LDSM4(al, sb + SM_XL + aoff);

        uint32_t bh[4][4], bl[4][4];
        uint32_t brow = (uint32_t)((ks * 16 + lrow) * 144) + lcol;
#pragma unroll
        for (int np = 0; np < 4; np++) {
            LDSM4T(bh[np], sb + SM_MH + brow + np * 32);
            LDSM4T(bl[np], sb + SM_ML + brow + np * 32);
        }
#pragma unroll
        for (int nt = 0; nt < 8; nt++) {
            uint32_t bh0 = bh[nt >> 1][(nt & 1) * 2], bh1 = bh[nt >> 1][(nt & 1) * 2 + 1];
            uint32_t bl0 = bl[nt >> 1][(nt & 1) * 2], bl1 = bl[nt >> 1][(nt & 1) * 2 + 1];
            MMA16816(d[nt], ah, bh0, bh1);
            MMA16816(d[nt], al, bh0, bh1);
            MMA16816(d[nt], ah, bl0, bl1);
        }
    }

    // epilogue: n-tiles 0-3 = yl cols, 4-7 = yr same cols (thread-local pairing)
    float* yb = y + ((size_t)b * P_ + pbase) * 128;
    int r0 = w * 16 + (lane >> 2);
    int jc = (lane & 3) * 2;
#define CLIP01(v) fminf(fmaxf((v), 0.f), 1.f)
#pragma unroll
    for (int nt = 0; nt < 4; nt++) {
        int col = nt * 8 + jc;
#pragma unroll
        for (int half = 0; half < 2; half++) {
            int p = r0 + half * 8;
            float l0 = d[nt][half * 2],     l1 = d[nt][half * 2 + 1];
            float q0 = d[nt + 4][half * 2], q1 = d[nt + 4][half * 2 + 1];
            float s0 = l0 + q0, s1 = l1 + q1;
            float e0 = l0 - q0, e1 = l1 - q1;
            float* row = yb + (size_t)p * 128 + col;
            *(float2*)(row)      = make_float2(CLIP01(s0),       CLIP01(s1));
            *(float2*)(row + 32) = make_float2(CLIP01(s0 - 1.f), CLIP01(s1 - 1.f));
            *(float2*)(row + 64) = make_float2(CLIP01(e0),       CLIP01(e1));
            *(float2*)(row + 96) = make_float2(CLIP01(-e0),      CLIP01(-e1));
        }
    }
#undef CLIP01
}

// ---------------------------------------------------------------------------
// Kernel 5: reduce 64 h partials + leaky, then v_encode = h @ W2 + b2.
// ---------------------------------------------------------------------------
__global__ void __launch_bounds__(1024) k_venc(const float* __restrict__ b1,
                                               const float* __restrict__ W2,
                                               const float* __restrict__ b2,
                                               float* __restrict__ out) {
    int b = blockIdx.x;
    int tid = threadIdx.x;
    __shared__ float sh[L_];
    __shared__ float red[4][L_];

    if (tid < L_) {
        float s = b1[tid];
#pragma unroll 8
        for (int ks = 0; ks < 64; ks++) s += g_hp[(size_t)(ks * B_ + b) * L_ + tid];
        sh[tid] = (s >= 0.f) ? s : 0.01f * s;
    }
    __syncthreads();

    int j = tid & 255, sl = tid >> 8;
    float a = 0.f;
    const float* wp = W2 + (size_t)(sl * 64) * L_ + j;
#pragma unroll 8
    for (int k = 0; k < 64; k++)
        a += sh[sl * 64 + k] * wp[(size_t)k * L_];
    red[sl][j] = a;
    __syncthreads();
    if (sl == 0)
        out[YSZ + b * L_ + j] = red[0][j] + red[1][j] + red[2][j] + red[3][j] + b2[j];
}

// ---------------------------------------------------------------------------
extern "C" void kernel_launch(void* const* d_in, const int* in_sizes, int n_in,
                              void* d_out, int out_size) {
    const float* x    = (const float*)d_in[0];
    const float* lat  = (const float*)d_in[1];
    const float* gu   = (const float*)d_in[2];
    const float* Kl   = (const float*)d_in[3];
    const float* Kr   = (const float*)d_in[4];
    const float* temp = (const float*)d_in[5];
    const float* W1   = (const float*)d_in[6];
    const float* b1   = (const float*)d_in[7];
    const float* W2   = (const float*)d_in[8];
    const float* b2   = (const float*)d_in[9];
    float* out = (float*)d_out;

    cudaFuncSetAttribute(k_main, cudaFuncAttributeMaxDynamicSharedMemorySize, SM_TOT);

    k_logits<<<dim3(128, 2), 256>>>(lat, Kl, Kr);
    k_sg<<<64, 256>>>(gu, temp);
    k_h_part<<<512, 256>>>(W1);
    k_main<<<dim3(64, 32), 256, SM_TOT>>>(x, out);   // slot 4: ncu-sampled
    k_venc<<<32, 1024>>>(b1, W2, b2, out);
}

// round 8
// speedup vs baseline: 2.6118x; 1.1267x over previous
#include <cuda_runtime.h>
#include <cuda_bf16.h>
#include <cstdint>

#define EPSF 1.1920928955078125e-07f

// Problem constants
#define B_   32
#define P_   8192
#define SI_  64
#define SO_  32
#define L_   256
#define C_   4096          // 2 * SI * SO
#define YSZ  33554432      // B*P*128

// Device scratch (no allocations allowed)
__device__ float g_logits[B_ * C_];
__device__ float g_V[B_ * C_];
__device__ float g_hp[64 * B_ * L_];          // 64-way split-K partials for h
__device__ __nv_bfloat16 g_mh[B_ * C_];       // mask hi (bf16)
__device__ __nv_bfloat16 g_ml[B_ * C_];       // mask lo residual (bf16)

// ---------------------------------------------------------------------------
// Kernel 1: logits[b,c] = sum_l latent[b,l] * K[side(c)][l, i, o]
// ---------------------------------------------------------------------------
__global__ void __launch_bounds__(256) k_logits(const float* __restrict__ lat,
                                                const float* __restrict__ Kl,
                                                const float* __restrict__ Kr) {
    __shared__ float slat[16 * L_];
    int bt = blockIdx.y;
    for (int k = threadIdx.x; k < 16 * L_; k += 256)
        slat[k] = lat[bt * 16 * L_ + k];
    __syncthreads();

    int c  = blockIdx.x * 32 + (threadIdx.x & 31);
    int bg = threadIdx.x >> 5;
    const float* Ksrc = (c & 2048) ? Kr : Kl;
    int cc = c & 2047;

    float a0 = 0.f, a1 = 0.f;
    const float* s0 = slat + (bg * 2) * L_;
    const float* s1 = s0 + L_;
#pragma unroll 2
    for (int l = 0; l < L_; l += 8) {
        float kv[8];
#pragma unroll
        for (int u = 0; u < 8; u++) kv[u] = Ksrc[(size_t)(l + u) * 2048 + cc];
#pragma unroll
        for (int u = 0; u < 8; u++) {
            a0 += s0[l + u] * kv[u];
            a1 += s1[l + u] * kv[u];
        }
    }
    int b = bt * 16 + bg * 2;
    g_logits[(size_t)b * C_ + c]       = a0;
    g_logits[(size_t)(b + 1) * C_ + c] = a1;
}

// ---------------------------------------------------------------------------
// Kernel 2: block per (b, side): softmax over i (-> g_V), gumbel-softmax
// (-> g_mh/g_ml bf16 hi/lo split). grid 64 x 256.
// ---------------------------------------------------------------------------
__global__ void __launch_bounds__(256) k_sg(const float* __restrict__ gu,
                                            const float* __restrict__ temp) {
    __shared__ float sl[SI_ * 33];
    __shared__ float red[8][32];
    __shared__ float red2[8][32];

    int b = blockIdx.x >> 1, side = blockIdx.x & 1;
    int tid = threadIdx.x, w = tid >> 5, lane = tid & 31;
    int gbase = b * C_ + side * 2048;

    for (int idx = tid; idx < 2048; idx += 256)
        sl[(idx >> 5) * 33 + (idx & 31)] = g_logits[gbase + idx];
    __syncthreads();

    float v[8];
    float mx = -1e30f;
#pragma unroll
    for (int k = 0; k < 8; k++) { v[k] = sl[(w * 8 + k) * 33 + lane]; mx = fmaxf(mx, v[k]); }
    red[w][lane] = mx;
    __syncthreads();
    float gm = red[0][lane];
#pragma unroll
    for (int q = 1; q < 8; q++) gm = fmaxf(gm, red[q][lane]);
    float s = 0.f;
#pragma unroll
    for (int k = 0; k < 8; k++) { v[k] = __expf(v[k] - gm); s += v[k]; }
    red2[w][lane] = s;
    __syncthreads();
    float tot = 0.f;
#pragma unroll
    for (int q = 0; q < 8; q++) tot += red2[q][lane];
    float inv = 1.0f / tot;
#pragma unroll
    for (int k = 0; k < 8; k++) { v[k] *= inv; g_V[gbase + (w * 8 + k) * 32 + lane] = v[k]; }

    __syncthreads();
    for (int idx = tid; idx < 2048; idx += 256)
        sl[(idx >> 5) * 33 + (idx & 31)] = gu[gbase + idx];
    __syncthreads();

    float tc = fmaxf(fminf(fmaxf(temp[0], EPSF), 2.0f), EPSF);
    float invt = 1.0f / tc;

    mx = -1e30f;
#pragma unroll
    for (int k = 0; k < 8; k++) {
        float u = fmaxf(sl[(w * 8 + k) * 33 + lane], EPSF);
        float g = -__logf(-__logf(u) + EPSF);
        float lg = (__logf(v[k] + EPSF) + g) * invt;
        v[k] = lg; mx = fmaxf(mx, lg);
    }
    red[w][lane] = mx;
    __syncthreads();
    gm = red[0][lane];
#pragma unroll
    for (int q = 1; q < 8; q++) gm = fmaxf(gm, red[q][lane]);
    s = 0.f;
#pragma unroll
    for (int k = 0; k < 8; k++) { v[k] = __expf(v[k] - gm); s += v[k]; }
    red2[w][lane] = s;
    __syncthreads();
    tot = 0.f;
#pragma unroll
    for (int q = 0; q < 8; q++) tot += red2[q][lane];
    inv = 1.0f / tot;

    // masks -> bf16 hi/lo split, layout [b][i][side*32 + o]
#pragma unroll
    for (int k = 0; k < 8; k++) {
        float mv = v[k] * inv;
        __nv_bfloat16 hi = __float2bfloat16_rn(mv);
        __nv_bfloat16 lo = __float2bfloat16_rn(mv - __bfloat162float(hi));
        size_t idx = (size_t)b * C_ + (w * 8 + k) * 64 + side * 32 + lane;
        g_mh[idx] = hi;
        g_ml[idx] = lo;
    }
}

// ---------------------------------------------------------------------------
// Kernel 3: 64-way split-K h partials; W1 read exactly once.
// ---------------------------------------------------------------------------
__global__ void __launch_bounds__(256) k_h_part(const float* __restrict__ W1) {
    int jt = blockIdx.x & 7;
    int ks = blockIdx.x >> 3;   // 0..63, 64 k each

    __shared__ float Vs[B_ * 68];
    for (int idx = threadIdx.x; idx < B_ * 64; idx += 256) {
        int b = idx >> 6, k = idx & 63;
        Vs[b * 68 + k] = g_V[b * C_ + ks * 64 + k];
    }
    __syncthreads();

    int j  = jt * 32 + (threadIdx.x & 31);
    int bg = threadIdx.x >> 5;

    float acc[4] = {0.f, 0.f, 0.f, 0.f};
    const float* wp = W1 + (size_t)(ks * 64) * 256 + j;
#pragma unroll
    for (int kb = 0; kb < 8; kb++) {
        float wv[8];
#pragma unroll
        for (int u = 0; u < 8; u++) wv[u] = wp[(size_t)(kb * 8 + u) * 256];
#pragma unroll
        for (int u = 0; u < 8; u++) {
            int k = kb * 8 + u;
#pragma unroll
            for (int q = 0; q < 4; q++)
                acc[q] += Vs[(bg * 4 + q) * 68 + k] * wv[u];
        }
    }
#pragma unroll
    for (int q = 0; q < 4; q++)
        g_hp[(size_t)(ks * B_ + bg * 4 + q) * L_ + j] = acc[q];
}

// ---------------------------------------------------------------------------
// Kernel 4 (main GEMM, tensor cores + coalesced epilogue).
// bf16 3-term split HMMA; fragments staged through smem so stores are
// full-line STG.128 (4 wavefronts/instr vs 8 for the scattered path).
// ---------------------------------------------------------------------------
#define LDSM4(r, a) \
    asm volatile("ldmatrix.sync.aligned.m8n8.x4.shared.b16 {%0,%1,%2,%3}, [%4];" \
        : "=r"((r)[0]), "=r"((r)[1]), "=r"((r)[2]), "=r"((r)[3]) : "r"(a))
#define LDSM4T(r, a) \
    asm volatile("ldmatrix.sync.aligned.m8n8.x4.trans.shared.b16 {%0,%1,%2,%3}, [%4];" \
        : "=r"((r)[0]), "=r"((r)[1]), "=r"((r)[2]), "=r"((r)[3]) : "r"(a))
#define MMA16816(d, a, b0, b1) \
    asm volatile("mma.sync.aligned.m16n8k16.row.col.f32.bf16.bf16.f32 " \
        "{%0,%1,%2,%3}, {%4,%5,%6,%7}, {%8,%9}, {%0,%1,%2,%3};" \
        : "+f"((d)[0]), "+f"((d)[1]), "+f"((d)[2]), "+f"((d)[3]) \
        : "r"((a)[0]), "r"((a)[1]), "r"((a)[2]), "r"((a)[3]), "r"(b0), "r"(b1))

// smem byte offsets (mask/X rows padded: 64 bf16 -> 144 B)
#define SM_MH 0
#define SM_ML 9216
#define SM_XH 18432
#define SM_XL 36864
#define SM_TOT 55296
// epilogue buffer overlays X region: [128 rows][72 floats] = 36864 B

extern __shared__ char smc[];

__global__ void __launch_bounds__(256) k_main(const float* __restrict__ x,
                                              float* __restrict__ y) {
    int tid = threadIdx.x, lane = tid & 31, w = tid >> 5;
    int b = blockIdx.y;
    int pbase = blockIdx.x * 128;

    uint32_t sb = (uint32_t)__cvta_generic_to_shared(smc);

    // stage masks (bf16 hi/lo), 64 rows x 128B -> padded 144B rows
    const uint4* mh4 = (const uint4*)(g_mh + (size_t)b * C_);
    const uint4* ml4 = (const uint4*)(g_ml + (size_t)b * C_);
#pragma unroll
    for (int k = 0; k < 2; k++) {
        int idx = tid + k * 256;
        int row = idx >> 3, ch = idx & 7;
        *(uint4*)(smc + SM_MH + row * 144 + ch * 16) = mh4[idx];
        *(uint4*)(smc + SM_ML + row * 144 + ch * 16) = ml4[idx];
    }

    // stage X: load f32, split to bf16 hi + lo residual
    const float4* xg = (const float4*)(x + ((size_t)b * P_ + pbase) * SI_);
#pragma unroll
    for (int k = 0; k < 8; k++) {
        int idx = tid + k * 256;
        int row = idx >> 4, f4 = idx & 15;
        float4 v = xg[idx];
        __nv_bfloat16 h0 = __float2bfloat16_rn(v.x);
        __nv_bfloat16 h1 = __float2bfloat16_rn(v.y);
        __nv_bfloat16 h2 = __float2bfloat16_rn(v.z);
        __nv_bfloat16 h3 = __float2bfloat16_rn(v.w);
        __nv_bfloat16 l0 = __float2bfloat16_rn(v.x - __bfloat162float(h0));
        __nv_bfloat16 l1 = __float2bfloat16_rn(v.y - __bfloat162float(h1));
        __nv_bfloat16 l2 = __float2bfloat16_rn(v.z - __bfloat162float(h2));
        __nv_bfloat16 l3 = __float2bfloat16_rn(v.w - __bfloat162float(h3));
        __nv_bfloat162 hA = {h0, h1}, hB = {h2, h3};
        __nv_bfloat162 lA = {l0, l1}, lB = {l2, l3};
        uint2 hp = make_uint2(*(uint32_t*)&hA, *(uint32_t*)&hB);
        uint2 lp = make_uint2(*(uint32_t*)&lA, *(uint32_t*)&lB);
        *(uint2*)(smc + SM_XH + row * 144 + f4 * 8) = hp;
        *(uint2*)(smc + SM_XL + row * 144 + f4 * 8) = lp;
    }
    __syncthreads();

    float d[8][4];
#pragma unroll
    for (int nt = 0; nt < 8; nt++)
#pragma unroll
        for (int q = 0; q < 4; q++) d[nt][q] = 0.f;

    int lrow = lane & 15;
    uint32_t lcol = (lane >> 4) * 16;

#pragma unroll
    for (int ks = 0; ks < 4; ks++) {
        uint32_t ah[4], al[4];
        uint32_t aoff = (uint32_t)((w * 16 + lrow) * 144 + ks * 32) + lcol;
        LDSM4(ah, sb + SM_XH + aoff);
        LDSM4(al, sb + SM_XL + aoff);

        uint32_t bh[4][4], bl[4][4];
        uint32_t brow = (uint32_t)((ks * 16 + lrow) * 144) + lcol;
#pragma unroll
        for (int np = 0; np < 4; np++) {
            LDSM4T(bh[np], sb + SM_MH + brow + np * 32);
            LDSM4T(bl[np], sb + SM_ML + brow + np * 32);
        }
#pragma unroll
        for (int nt = 0; nt < 8; nt++) {
            uint32_t bh0 = bh[nt >> 1][(nt & 1) * 2], bh1 = bh[nt >> 1][(nt & 1) * 2 + 1];
            uint32_t bl0 = bl[nt >> 1][(nt & 1) * 2], bl1 = bl[nt >> 1][(nt & 1) * 2 + 1];
            MMA16816(d[nt], ah, bh0, bh1);
            MMA16816(d[nt], al, bh0, bh1);
            MMA16816(d[nt], ah, bl0, bl1);
        }
    }

    // ---- epilogue: fragments -> smem [128][72], then coalesced STG.128 ----
    __syncthreads();   // all LDSM reads of X region complete
    float* eb = (float*)(smc + SM_XH);
    int r0 = w * 16 + (lane >> 2);
    int cb = (lane & 3) * 2;
#pragma unroll
    for (int nt = 0; nt < 8; nt++) {
        int col = nt * 8 + cb;               // yl cols 0..31, yr cols 32..63
        *(float2*)(eb + (size_t)r0 * 72 + col)       = make_float2(d[nt][0], d[nt][1]);
        *(float2*)(eb + (size_t)(r0 + 8) * 72 + col) = make_float2(d[nt][2], d[nt][3]);
    }
    __syncwarp();      // warp reads only its own 16 rows

    float* yb = y + ((size_t)b * P_ + pbase) * 128;
    int ch = lane & 7;
#define CLIP01(v) fminf(fmaxf((v), 0.f), 1.f)
#pragma unroll
    for (int rg = 0; rg < 4; rg++) {
        int row = w * 16 + rg * 4 + (lane >> 3);
        float4 vl = *(float4*)(eb + (size_t)row * 72 + ch * 4);
        float4 vr = *(float4*)(eb + (size_t)row * 72 + 32 + ch * 4);
        float s0 = vl.x + vr.x, s1 = vl.y + vr.y, s2 = vl.z + vr.z, s3 = vl.w + vr.w;
        float e0 = vl.x - vr.x, e1 = vl.y - vr.y, e2 = vl.z - vr.z, e3 = vl.w - vr.w;
        float* orow = yb + (size_t)row * 128 + ch * 4;
        float4 o;
        o.x = CLIP01(s0); o.y = CLIP01(s1); o.z = CLIP01(s2); o.w = CLIP01(s3);
        *(float4*)(orow) = o;
        o.x = CLIP01(s0 - 1.f); o.y = CLIP01(s1 - 1.f); o.z = CLIP01(s2 - 1.f); o.w = CLIP01(s3 - 1.f);
        *(float4*)(orow + 32) = o;
        o.x = CLIP01(e0); o.y = CLIP01(e1); o.z = CLIP01(e2); o.w = CLIP01(e3);
        *(float4*)(orow + 64) = o;
        o.x = CLIP01(-e0); o.y = CLIP01(-e1); o.z = CLIP01(-e2); o.w = CLIP01(-e3);
        *(float4*)(orow + 96) = o;
    }
#undef CLIP01
}

// ---------------------------------------------------------------------------
// Kernel 5: reduce 64 h partials (all 1024 threads) + leaky, then
// v_encode = h @ W2 + b2.
// ---------------------------------------------------------------------------
__global__ void __launch_bounds__(1024) k_venc(const float* __restrict__ b1,
                                               const float* __restrict__ W2,
                                               const float* __restrict__ b2,
                                               float* __restrict__ out) {
    int b = blockIdx.x;
    int tid = threadIdx.x;
    __shared__ float sh[L_];
    __shared__ float red[4][L_];

    int j = tid & 255, sl = tid >> 8;
    {
        float s = 0.f;
#pragma unroll 4
        for (int ks = sl * 16; ks < sl * 16 + 16; ks++)
            s += g_hp[(size_t)(ks * B_ + b) * L_ + j];
        red[sl][j] = s;
    }
    __syncthreads();
    if (sl == 0) {
        float s = b1[j] + red[0][j] + red[1][j] + red[2][j] + red[3][j];
        sh[j] = (s >= 0.f) ? s : 0.01f * s;
    }
    __syncthreads();

    float a = 0.f;
    const float* wp = W2 + (size_t)(sl * 64) * L_ + j;
#pragma unroll 8
    for (int k = 0; k < 64; k++)
        a += sh[sl * 64 + k] * wp[(size_t)k * L_];
    red[sl][j] = a;
    __syncthreads();
    if (sl == 0)
        out[YSZ + b * L_ + j] = red[0][j] + red[1][j] + red[2][j] + red[3][j] + b2[j];
}

// ---------------------------------------------------------------------------
extern "C" void kernel_launch(void* const* d_in, const int* in_sizes, int n_in,
                              void* d_out, int out_size) {
    const float* x    = (const float*)d_in[0];
    const float* lat  = (const float*)d_in[1];
    const float* gu   = (const float*)d_in[2];
    const float* Kl   = (const float*)d_in[3];
    const float* Kr   = (const float*)d_in[4];
    const float* temp = (const float*)d_in[5];
    const float* W1   = (const float*)d_in[6];
    const float* b1   = (const float*)d_in[7];
    const float* W2   = (const float*)d_in[8];
    const float* b2   = (const float*)d_in[9];
    float* out = (float*)d_out;

    cudaFuncSetAttribute(k_main, cudaFuncAttributeMaxDynamicSharedMemorySize, SM_TOT);

    // Fork-join: h-chain (h_part -> venc) depends only on g_V; run it on a
    // side stream concurrently with k_main. Capture-safe fork via events.
    cudaStream_t s1;
    cudaEvent_t e1, e2;
    cudaStreamCreateWithFlags(&s1, cudaStreamNonBlocking);
    cudaEventCreateWithFlags(&e1, cudaEventDisableTiming);
    cudaEventCreateWithFlags(&e2, cudaEventDisableTiming);

    k_logits<<<dim3(128, 2), 256>>>(lat, Kl, Kr);
    k_sg<<<64, 256>>>(gu, temp);

    cudaEventRecord(e1, 0);
    cudaStreamWaitEvent(s1, e1, 0);
    k_h_part<<<512, 256, 0, s1>>>(W1);
    k_venc<<<32, 1024, 0, s1>>>(b1, W2, b2, out);
    cudaEventRecord(e2, s1);

    k_main<<<dim3(64, 32), 256, SM_TOT>>>(x, out);   // overlaps side stream

    cudaStreamWaitEvent(0, e2, 0);
}

// round 9
// speedup vs baseline: 2.7806x; 1.0646x over previous
#include <cuda_runtime.h>
#include <cuda_bf16.h>
#include <cstdint>

#define EPSF 1.1920928955078125e-07f

// Problem constants
#define B_   32
#define P_   8192
#define SI_  64
#define SO_  32
#define L_   256
#define C_   4096          // 2 * SI * SO
#define YSZ  33554432      // B*P*128

// Device scratch (no allocations allowed)
__device__ float g_logits[B_ * C_];
__device__ float g_V[B_ * C_];
__device__ float g_hp[64 * B_ * L_];          // 64-way split-K partials for h
__device__ __nv_bfloat16 g_mh[B_ * C_];       // mask hi (bf16)
__device__ __nv_bfloat16 g_ml[B_ * C_];       // mask lo residual (bf16)

// ---------------------------------------------------------------------------
// Kernel 1: logits[b,c] = sum_l latent[b,l] * K[side(c)][l, i, o]
// grid 128 (32-col tiles), block 256 = (32 c x 8 bg), 4 batches per thread.
// K read exactly once (16 MB); unroll-8 K prefetch for MLP.
// ---------------------------------------------------------------------------
__global__ void __launch_bounds__(256) k_logits(const float* __restrict__ lat,
                                                const float* __restrict__ Kl,
                                                const float* __restrict__ Kr) {
    __shared__ float slat[B_ * L_];  // 32 KB
    for (int k = threadIdx.x; k < B_ * L_; k += 256) slat[k] = lat[k];
    __syncthreads();

    int c  = blockIdx.x * 32 + (threadIdx.x & 31);
    int bg = threadIdx.x >> 5;                // 0..7 -> batches bg*4..bg*4+3
    const float* Ksrc = (c & 2048) ? Kr : Kl;
    int cc = c & 2047;

    float acc[4] = {0.f, 0.f, 0.f, 0.f};
    const float* s0 = slat + (bg * 4) * L_;
#pragma unroll 4
    for (int l = 0; l < L_; l += 8) {
        float kv[8];
#pragma unroll
        for (int u = 0; u < 8; u++) kv[u] = Ksrc[(size_t)(l + u) * 2048 + cc];
#pragma unroll
        for (int u = 0; u < 8; u++) {
#pragma unroll
            for (int q = 0; q < 4; q++)
                acc[q] += s0[q * L_ + l + u] * kv[u];
        }
    }
#pragma unroll
    for (int q = 0; q < 4; q++)
        g_logits[(size_t)(bg * 4 + q) * C_ + c] = acc[q];
}

// ---------------------------------------------------------------------------
// Kernel 2: warp-per-(b,side,o) column softmax + gumbel-softmax, shfl-only
// (no block syncs). Lane handles i=lane and i=lane+32. grid 256 x 256.
// Writes g_V and the bf16 hi/lo mask split (layout [b][i][side*32+o]).
// ---------------------------------------------------------------------------
__device__ __forceinline__ float warp_max(float v) {
#pragma unroll
    for (int m = 16; m > 0; m >>= 1) v = fmaxf(v, __shfl_xor_sync(0xffffffffu, v, m));
    return v;
}
__device__ __forceinline__ float warp_sum(float v) {
#pragma unroll
    for (int m = 16; m > 0; m >>= 1) v += __shfl_xor_sync(0xffffffffu, v, m);
    return v;
}

__global__ void __launch_bounds__(256) k_sg(const float* __restrict__ gu,
                                            const float* __restrict__ temp) {
    int w    = (blockIdx.x * blockDim.x + threadIdx.x) >> 5;  // 0..2047
    int lane = threadIdx.x & 31;
    int b    = w >> 6;
    int rem  = w & 63;                 // side*32 + o
    int side = rem >> 5, o = rem & 31;
    int base = b * C_ + side * 2048 + o;

    float a0 = g_logits[base + lane * 32];
    float a1 = g_logits[base + (lane + 32) * 32];
    float mx = warp_max(fmaxf(a0, a1));
    float e0 = __expf(a0 - mx), e1 = __expf(a1 - mx);
    float inv = 1.0f / warp_sum(e0 + e1);
    float p0 = e0 * inv, p1 = e1 * inv;
    g_V[base + lane * 32]        = p0;
    g_V[base + (lane + 32) * 32] = p1;

    float tc = fmaxf(fminf(fmaxf(temp[0], EPSF), 2.0f), EPSF);
    float invt = 1.0f / tc;

    float u0 = fmaxf(gu[base + lane * 32], EPSF);
    float u1 = fmaxf(gu[base + (lane + 32) * 32], EPSF);
    float g0 = -__logf(-__logf(u0) + EPSF);
    float g1 = -__logf(-__logf(u1) + EPSF);
    float l0 = (__logf(p0 + EPSF) + g0) * invt;
    float l1 = (__logf(p1 + EPSF) + g1) * invt;
    mx = warp_max(fmaxf(l0, l1));
    e0 = __expf(l0 - mx); e1 = __expf(l1 - mx);
    inv = 1.0f / warp_sum(e0 + e1);
    float m0 = e0 * inv, m1 = e1 * inv;

    // bf16 hi/lo split, layout [b][i][side*32 + o]
    __nv_bfloat16 h0 = __float2bfloat16_rn(m0);
    __nv_bfloat16 h1 = __float2bfloat16_rn(m1);
    __nv_bfloat16 q0 = __float2bfloat16_rn(m0 - __bfloat162float(h0));
    __nv_bfloat16 q1 = __float2bfloat16_rn(m1 - __bfloat162float(h1));
    size_t i0 = (size_t)b * C_ + lane * 64 + side * 32 + o;
    size_t i1 = (size_t)b * C_ + (lane + 32) * 64 + side * 32 + o;
    g_mh[i0] = h0; g_ml[i0] = q0;
    g_mh[i1] = h1; g_ml[i1] = q1;
}

// ---------------------------------------------------------------------------
// Kernel 3: 64-way split-K h partials; W1 read exactly once.
// ---------------------------------------------------------------------------
__global__ void __launch_bounds__(256) k_h_part(const float* __restrict__ W1) {
    int jt = blockIdx.x & 7;
    int ks = blockIdx.x >> 3;   // 0..63, 64 k each

    __shared__ float Vs[B_ * 68];
    for (int idx = threadIdx.x; idx < B_ * 64; idx += 256) {
        int b = idx >> 6, k = idx & 63;
        Vs[b * 68 + k] = g_V[b * C_ + ks * 64 + k];
    }
    __syncthreads();

    int j  = jt * 32 + (threadIdx.x & 31);
    int bg = threadIdx.x >> 5;

    float acc[4] = {0.f, 0.f, 0.f, 0.f};
    const float* wp = W1 + (size_t)(ks * 64) * 256 + j;
#pragma unroll
    for (int kb = 0; kb < 8; kb++) {
        float wv[8];
#pragma unroll
        for (int u = 0; u < 8; u++) wv[u] = wp[(size_t)(kb * 8 + u) * 256];
#pragma unroll
        for (int u = 0; u < 8; u++) {
            int k = kb * 8 + u;
#pragma unroll
            for (int q = 0; q < 4; q++)
                acc[q] += Vs[(bg * 4 + q) * 68 + k] * wv[u];
        }
    }
#pragma unroll
    for (int q = 0; q < 4; q++)
        g_hp[(size_t)(ks * B_ + bg * 4 + q) * L_ + j] = acc[q];
}

// ---------------------------------------------------------------------------
// Kernel 4 (main GEMM, tensor cores + coalesced epilogue).
// bf16 3-term split HMMA; fragments staged through smem -> STG.128.
// ---------------------------------------------------------------------------
#define LDSM4(r, a) \
    asm volatile("ldmatrix.sync.aligned.m8n8.x4.shared.b16 {%0,%1,%2,%3}, [%4];" \
        : "=r"((r)[0]), "=r"((r)[1]), "=r"((r)[2]), "=r"((r)[3]) : "r"(a))
#define LDSM4T(r, a) \
    asm volatile("ldmatrix.sync.aligned.m8n8.x4.trans.shared.b16 {%0,%1,%2,%3}, [%4];" \
        : "=r"((r)[0]), "=r"((r)[1]), "=r"((r)[2]), "=r"((r)[3]) : "r"(a))
#define MMA16816(d, a, b0, b1) \
    asm volatile("mma.sync.aligned.m16n8k16.row.col.f32.bf16.bf16.f32 " \
        "{%0,%1,%2,%3}, {%4,%5,%6,%7}, {%8,%9}, {%0,%1,%2,%3};" \
        : "+f"((d)[0]), "+f"((d)[1]), "+f"((d)[2]), "+f"((d)[3]) \
        : "r"((a)[0]), "r"((a)[1]), "r"((a)[2]), "r"((a)[3]), "r"(b0), "r"(b1))

#define SM_MH 0
#define SM_ML 9216
#define SM_XH 18432
#define SM_XL 36864
#define SM_TOT 55296

extern __shared__ char smc[];

__global__ void __launch_bounds__(256) k_main(const float* __restrict__ x,
                                              float* __restrict__ y) {
    int tid = threadIdx.x, lane = tid & 31, w = tid >> 5;
    int b = blockIdx.y;
    int pbase = blockIdx.x * 128;

    uint32_t sb = (uint32_t)__cvta_generic_to_shared(smc);

    const uint4* mh4 = (const uint4*)(g_mh + (size_t)b * C_);
    const uint4* ml4 = (const uint4*)(g_ml + (size_t)b * C_);
#pragma unroll
    for (int k = 0; k < 2; k++) {
        int idx = tid + k * 256;
        int row = idx >> 3, ch = idx & 7;
        *(uint4*)(smc + SM_MH + row * 144 + ch * 16) = mh4[idx];
        *(uint4*)(smc + SM_ML + row * 144 + ch * 16) = ml4[idx];
    }

    const float4* xg = (const float4*)(x + ((size_t)b * P_ + pbase) * SI_);
#pragma unroll
    for (int k = 0; k < 8; k++) {
        int idx = tid + k * 256;
        int row = idx >> 4, f4 = idx & 15;
        float4 v = xg[idx];
        __nv_bfloat16 h0 = __float2bfloat16_rn(v.x);
        __nv_bfloat16 h1 = __float2bfloat16_rn(v.y);
        __nv_bfloat16 h2 = __float2bfloat16_rn(v.z);
        __nv_bfloat16 h3 = __float2bfloat16_rn(v.w);
        __nv_bfloat16 l0 = __float2bfloat16_rn(v.x - __bfloat162float(h0));
        __nv_bfloat16 l1 = __float2bfloat16_rn(v.y - __bfloat162float(h1));
        __nv_bfloat16 l2 = __float2bfloat16_rn(v.z - __bfloat162float(h2));
        __nv_bfloat16 l3 = __float2bfloat16_rn(v.w - __bfloat162float(h3));
        __nv_bfloat162 hA = {h0, h1}, hB = {h2, h3};
        __nv_bfloat162 lA = {l0, l1}, lB = {l2, l3};
        uint2 hp = make_uint2(*(uint32_t*)&hA, *(uint32_t*)&hB);
        uint2 lp = make_uint2(*(uint32_t*)&lA, *(uint32_t*)&lB);
        *(uint2*)(smc + SM_XH + row * 144 + f4 * 8) = hp;
        *(uint2*)(smc + SM_XL + row * 144 + f4 * 8) = lp;
    }
    __syncthreads();

    float d[8][4];
#pragma unroll
    for (int nt = 0; nt < 8; nt++)
#pragma unroll
        for (int q = 0; q < 4; q++) d[nt][q] = 0.f;

    int lrow = lane & 15;
    uint32_t lcol = (lane >> 4) * 16;

#pragma unroll
    for (int ks = 0; ks < 4; ks++) {
        uint32_t ah[4], al[4];
        uint32_t aoff = (uint32_t)((w * 16 + lrow) * 144 + ks * 32) + lcol;
        LDSM4(ah, sb + SM_XH + aoff);
        LDSM4(al, sb + SM_XL + aoff);

        uint32_t bh[4][4], bl[4][4];
        uint32_t brow = (uint32_t)((ks * 16 + lrow) * 144) + lcol;
#pragma unroll
        for (int np = 0; np < 4; np++) {
            LDSM4T(bh[np], sb + SM_MH + brow + np * 32);
            LDSM4T(bl[np], sb + SM_ML + brow + np * 32);
        }
#pragma unroll
        for (int nt = 0; nt < 8; nt++) {
            uint32_t bh0 = bh[nt >> 1][(nt & 1) * 2], bh1 = bh[nt >> 1][(nt & 1) * 2 + 1];
            uint32_t bl0 = bl[nt >> 1][(nt & 1) * 2], bl1 = bl[nt >> 1][(nt & 1) * 2 + 1];
            MMA16816(d[nt], ah, bh0, bh1);
            MMA16816(d[nt], al, bh0, bh1);
            MMA16816(d[nt], ah, bl0, bl1);
        }
    }

    // epilogue: fragments -> smem [128][72], then coalesced STG.128
    __syncthreads();
    float* eb = (float*)(smc + SM_XH);
    int r0 = w * 16 + (lane >> 2);
    int cb = (lane & 3) * 2;
#pragma unroll
    for (int nt = 0; nt < 8; nt++) {
        int col = nt * 8 + cb;
        *(float2*)(eb + (size_t)r0 * 72 + col)       = make_float2(d[nt][0], d[nt][1]);
        *(float2*)(eb + (size_t)(r0 + 8) * 72 + col) = make_float2(d[nt][2], d[nt][3]);
    }
    __syncwarp();

    float* yb = y + ((size_t)b * P_ + pbase) * 128;
    int ch = lane & 7;
#define CLIP01(v) fminf(fmaxf((v), 0.f), 1.f)
#pragma unroll
    for (int rg = 0; rg < 4; rg++) {
        int row = w * 16 + rg * 4 + (lane >> 3);
        float4 vl = *(float4*)(eb + (size_t)row * 72 + ch * 4);
        float4 vr = *(float4*)(eb + (size_t)row * 72 + 32 + ch * 4);
        float s0 = vl.x + vr.x, s1 = vl.y + vr.y, s2 = vl.z + vr.z, s3 = vl.w + vr.w;
        float e0 = vl.x - vr.x, e1 = vl.y - vr.y, e2 = vl.z - vr.z, e3 = vl.w - vr.w;
        float* orow = yb + (size_t)row * 128 + ch * 4;
        float4 o;
        o.x = CLIP01(s0); o.y = CLIP01(s1); o.z = CLIP01(s2); o.w = CLIP01(s3);
        *(float4*)(orow) = o;
        o.x = CLIP01(s0 - 1.f); o.y = CLIP01(s1 - 1.f); o.z = CLIP01(s2 - 1.f); o.w = CLIP01(s3 - 1.f);
        *(float4*)(orow + 32) = o;
        o.x = CLIP01(e0); o.y = CLIP01(e1); o.z = CLIP01(e2); o.w = CLIP01(e3);
        *(float4*)(orow + 64) = o;
        o.x = CLIP01(-e0); o.y = CLIP01(-e1); o.z = CLIP01(-e2); o.w = CLIP01(-e3);
        *(float4*)(orow + 96) = o;
    }
#undef CLIP01
}

// ---------------------------------------------------------------------------
// Kernel 5: reduce 64 h partials (all 1024 threads) + leaky, then
// v_encode = h @ W2 + b2.
// ---------------------------------------------------------------------------
__global__ void __launch_bounds__(1024) k_venc(const float* __restrict__ b1,
                                               const float* __restrict__ W2,
                                               const float* __restrict__ b2,
                                               float* __restrict__ out) {
    int b = blockIdx.x;
    int tid = threadIdx.x;
    __shared__ float sh[L_];
    __shared__ float red[4][L_];

    int j = tid & 255, sl = tid >> 8;
    {
        float s = 0.f;
#pragma unroll 4
        for (int ks = sl * 16; ks < sl * 16 + 16; ks++)
            s += g_hp[(size_t)(ks * B_ + b) * L_ + j];
        red[sl][j] = s;
    }
    __syncthreads();
    if (sl == 0) {
        float s = b1[j] + red[0][j] + red[1][j] + red[2][j] + red[3][j];
        sh[j] = (s >= 0.f) ? s : 0.01f * s;
    }
    __syncthreads();

    float a = 0.f;
    const float* wp = W2 + (size_t)(sl * 64) * L_ + j;
#pragma unroll 8
    for (int k = 0; k < 64; k++)
        a += sh[sl * 64 + k] * wp[(size_t)k * L_];
    red[sl][j] = a;
    __syncthreads();
    if (sl == 0)
        out[YSZ + b * L_ + j] = red[0][j] + red[1][j] + red[2][j] + red[3][j] + b2[j];
}

// ---------------------------------------------------------------------------
extern "C" void kernel_launch(void* const* d_in, const int* in_sizes, int n_in,
                              void* d_out, int out_size) {
    const float* x    = (const float*)d_in[0];
    const float* lat  = (const float*)d_in[1];
    const float* gu   = (const float*)d_in[2];
    const float* Kl   = (const float*)d_in[3];
    const float* Kr   = (const float*)d_in[4];
    const float* temp = (const float*)d_in[5];
    const float* W1   = (const float*)d_in[6];
    const float* b1   = (const float*)d_in[7];
    const float* W2   = (const float*)d_in[8];
    const float* b2   = (const float*)d_in[9];
    float* out = (float*)d_out;

    cudaFuncSetAttribute(k_main, cudaFuncAttributeMaxDynamicSharedMemorySize, SM_TOT);

    // Fork-join: h-chain depends only on g_V; overlaps k_main.
    cudaStream_t s1;
    cudaEvent_t e1, e2;
    cudaStreamCreateWithFlags(&s1, cudaStreamNonBlocking);
    cudaEventCreateWithFlags(&e1, cudaEventDisableTiming);
    cudaEventCreateWithFlags(&e2, cudaEventDisableTiming);

    k_logits<<<128, 256>>>(lat, Kl, Kr);
    k_sg<<<256, 256>>>(gu, temp);

    cudaEventRecord(e1, 0);
    cudaStreamWaitEvent(s1, e1, 0);
    k_h_part<<<512, 256, 0, s1>>>(W1);
    k_venc<<<32, 1024, 0, s1>>>(b1, W2, b2, out);
    cudaEventRecord(e2, s1);

    k_main<<<dim3(64, 32), 256, SM_TOT>>>(x, out);   // overlaps side stream

    cudaStreamWaitEvent(0, e2, 0);
}